// round 10
// baseline (speedup 1.0000x reference)
#include <cuda_runtime.h>
#include <cuda_bf16.h>
#include <math.h>
#include <stdint.h>

#define L_SEQ 256
#define B_SZ  512
#define KIN   15
#define KST   512
#define NLX   1536
#define NTOK  (L_SEQ*B_SZ)   // 131072
#define NBR   128            // persistent CTAs for recurrence
#define BSTR  520            // weight-slab row stride (bf16 elems), 1040B rows
#define ASTR  40             // A-chunk row stride (bf16 elems), 80B rows

typedef unsigned long long ull;
typedef __nv_bfloat16 bf16;

// ---------------- scratch (device globals; no allocation) ----------------
__device__ __align__(16) bf16 g_xe_hi[(size_t)NTOK*KST];
__device__ __align__(16) bf16 g_xe_lo[(size_t)NTOK*KST];
__device__ float g_Lx[(size_t)NTOK*NLX];
__device__ __align__(16) bf16 g_st_hi[(size_t)NTOK*KST];
__device__ __align__(16) bf16 g_st_lo[(size_t)NTOK*KST];
__device__ float g_ty[(size_t)(NTOK-B_SZ)*KST];
__device__ float g_h  [B_SZ*KST];
__device__ float g_hA [B_SZ*KST];
__device__ float g_hB [B_SZ*KST];
__device__ float g_acc[B_SZ*KST];
__device__ float g_zg [B_SZ*KST];
__device__ __align__(16) bf16 g_hs_hi[B_SZ*KST];
__device__ __align__(16) bf16 g_hs_lo[B_SZ*KST];
__device__ __align__(16) bf16 g_us_hi[B_SZ*KST];
__device__ __align__(16) bf16 g_us_lo[B_SZ*KST];
__device__ unsigned g_bar_count = 0;
__device__ volatile unsigned g_bar_gen = 0;

// fast activations (MUFU-based, ~1e-6 rel err, saturating at +-inf)
__device__ __forceinline__ float fsigmoid(float x) { return 1.f/(1.f + __expf(-x)); }
__device__ __forceinline__ float ftanh(float x) {
    float e = __expf(2.f*x);
    return 1.f - __fdividef(2.f, e + 1.f);
}

// ---------------- warp-MMA + async-copy primitives (sm_80+ baseline PTX) ----------------
__device__ __forceinline__ uint32_t smem_u32(const void* p) {
    uint32_t a;
    asm("{ .reg .u64 t; cvta.to.shared.u64 t, %1; cvt.u32.u64 %0, t; }" : "=r"(a) : "l"(p));
    return a;
}
__device__ __forceinline__ void ldsm4(uint32_t* r, uint32_t addr) {
    asm volatile("ldmatrix.sync.aligned.m8n8.x4.shared.b16 {%0,%1,%2,%3}, [%4];"
        : "=r"(r[0]), "=r"(r[1]), "=r"(r[2]), "=r"(r[3]) : "r"(addr));
}
__device__ __forceinline__ void mma16816(float* d, const uint32_t* a, uint32_t b0, uint32_t b1) {
    asm volatile("mma.sync.aligned.m16n8k16.row.col.f32.bf16.bf16.f32 "
        "{%0,%1,%2,%3}, {%4,%5,%6,%7}, {%8,%9}, {%0,%1,%2,%3};"
        : "+f"(d[0]), "+f"(d[1]), "+f"(d[2]), "+f"(d[3])
        : "r"(a[0]), "r"(a[1]), "r"(a[2]), "r"(a[3]), "r"(b0), "r"(b1));
}
__device__ __forceinline__ void cp16(uint32_t dst, const void* src) {
    asm volatile("cp.async.cg.shared.global [%0], [%1], 16;" :: "r"(dst), "l"(src));
}
#define CP_COMMIT() asm volatile("cp.async.commit_group;" ::: "memory")
#define CP_WAIT(n)  asm volatile("cp.async.wait_group %0;" :: "n"(n) : "memory")

__device__ __forceinline__ void split_store(bf16* hi, bf16* lo, size_t idx, float v) {
    bf16 h = __float2bfloat16(v);
    hi[idx] = h;
    lo[idx] = __float2bfloat16(v - __bfloat162float(h));
}

// software grid barrier across NBR CTAs (all resident: 1 CTA/SM via smem)
__device__ __forceinline__ void grid_sync() {
    __syncthreads();
    if (threadIdx.x == 0) {
        __threadfence();
        unsigned g = g_bar_gen;
        if (atomicAdd(&g_bar_count, 1u) == (unsigned)(NBR - 1)) {
            g_bar_count = 0;
            __threadfence();
            g_bar_gen = g + 1u;
        } else {
            while (g_bar_gen == g) { __nanosleep(40); }
            __threadfence();
        }
    }
    __syncthreads();
}

// ---------------- xe = tanh(x @ Win^T + bin), split to bf16 hi/lo ----------------
__global__ void embed_kernel(const float* __restrict__ seq,
                             const float* __restrict__ Win,
                             const float* __restrict__ bin) {
    int tok = blockIdx.x;
    __shared__ float xs[KIN];
    if (threadIdx.x < KIN) xs[threadIdx.x] = seq[(size_t)tok*16 + threadIdx.x];
    __syncthreads();
    for (int j = threadIdx.x; j < KST; j += blockDim.x) {
        float s = bin[j];
        const float* wr = Win + j*KIN;
        #pragma unroll
        for (int i = 0; i < KIN; i++) s += xs[i]*wr[i];
        split_store(g_xe_hi, g_xe_lo, (size_t)tok*KST + j, ftanh(s));
    }
}

// ---------------- split-bf16 GEMM: C = act(A @ B^T), tile 128x64, K=512, 512 thr ----------------
// cp.async 3-stage pipelined A chunks (k=32); B slab staged once. 16 warps = 8 m x 2 n32.
#define GS_WHI  0
#define GS_WLO  66560
#define GS_A    133120          // 3 bufs x (hi 10240 + lo 10240)
#define GS_ABUF 20480
#define GS_SMEM (GS_A + 3*GS_ABUF)   // 194560
template<int TANH>
__global__ void __launch_bounds__(512) gemm_split(
    const bf16* __restrict__ Ahi, const bf16* __restrict__ Alo,
    const float* __restrict__ B, float* __restrict__ C, int N)
{
    extern __shared__ char sm[];
    uint32_t smu = smem_u32(sm);
    int tid = threadIdx.x;
    int w = tid >> 5, lane = tid & 31;
    int bm = blockIdx.x*128, bn = blockIdx.y*64;

    // stage B slab: 64 rows x 512 k, split fp32 -> hi/lo bf16
    for (int e = tid; e < 64*KST; e += 512) {
        int n = e >> 9, k = e & (KST-1);
        float v = B[(size_t)(bn + n)*KST + k];
        bf16 h = __float2bfloat16(v);
        size_t o = (size_t)n*BSTR + k;
        ((bf16*)(sm + GS_WHI))[o] = h;
        ((bf16*)(sm + GS_WLO))[o] = __float2bfloat16(v - __bfloat162float(h));
    }

    float acc[4][4];
    #pragma unroll
    for (int i = 0; i < 4; i++) { acc[i][0]=0.f; acc[i][1]=0.f; acc[i][2]=0.f; acc[i][3]=0.f; }

    int mt = w & 7, nh = w >> 3;
    uint32_t a_off = ((uint32_t)(16*mt + (lane & 15))*ASTR + ((lane >> 4) << 3)) * 2;
    uint32_t b_row = (lane & 7) + ((lane & 16) >> 1);
    uint32_t b_k8  = (lane & 8);

    // A staging: 128 rows x 32 k; 4 thr/row, 8 elems (16B) each, hi + lo
    int srow = tid >> 2, skc = (tid & 3)*8;
    const bf16* ahp = Ahi + (size_t)(bm + srow)*KST + skc;
    const bf16* alp = Alo + (size_t)(bm + srow)*KST + skc;
    uint32_t sdst = (uint32_t)(srow*ASTR + skc)*2;

    // prologue: chunk 0
    {
        uint32_t d = smu + GS_A + sdst;
        cp16(d, ahp);
        cp16(d + 10240, alp);
        CP_COMMIT();
    }
    __syncthreads();   // B slab visible

    #pragma unroll 1
    for (int c = 0; c < 16; c++) {
        if (c + 1 < 16) {
            uint32_t d = smu + GS_A + ((c+1)%3)*GS_ABUF + sdst;
            cp16(d,         ahp + (c+1)*32);
            cp16(d + 10240, alp + (c+1)*32);
            CP_COMMIT();
            CP_WAIT(1);
        } else {
            CP_WAIT(0);
        }
        __syncthreads();
        uint32_t abase = smu + GS_A + (c%3)*GS_ABUF;
        #pragma unroll
        for (int ks = 0; ks < 2; ks++) {
            uint32_t ah[4], al[4];
            ldsm4(ah, abase + a_off + ks*32);
            ldsm4(al, abase + 10240 + a_off + ks*32);
            uint32_t kb = (uint32_t)(c*32 + ks*16 + b_k8)*2;
            #pragma unroll
            for (int p = 0; p < 2; p++) {
                uint32_t bh[4], bl[4];
                uint32_t bo = (uint32_t)(32*nh + 16*p + b_row)*BSTR*2 + kb;
                ldsm4(bh, smu + GS_WHI + bo);
                ldsm4(bl, smu + GS_WLO + bo);
                mma16816(acc[2*p],   ah, bh[0], bh[1]);
                mma16816(acc[2*p+1], ah, bh[2], bh[3]);
                mma16816(acc[2*p],   ah, bl[0], bl[1]);
                mma16816(acc[2*p+1], ah, bl[2], bl[3]);
                mma16816(acc[2*p],   al, bh[0], bh[1]);
                mma16816(acc[2*p+1], al, bh[2], bh[3]);
            }
        }
    }

    int rowl = bm + 16*mt + (lane >> 2);
    #pragma unroll
    for (int nt = 0; nt < 4; nt++) {
        int col = bn + 32*nh + 8*nt + 2*(lane & 3);
        #pragma unroll
        for (int rr = 0; rr < 2; rr++) {
            size_t ro = (size_t)(rowl + 8*rr)*N + col;
            float v0 = acc[nt][2*rr], v1 = acc[nt][2*rr+1];
            if (TANH) { v0 = ftanh(v0); v1 = ftanh(v1); }
            C[ro] = v0; C[ro + 1] = v1;
        }
    }
}

// ---------------- persistent recurrence kernel (warp-MMA, split-bf16, cp.async, 512 thr) ----------------
// 128 CTAs x 512 thr. CTA: b0 = (cta&7)*64 rows, j0 = (cta>>3)*32 state cols.
// Phase A: 16 warps = 4 m-tiles x 4 n16 groups over the 64 gate cols (z:0-31, r:32-63).
// Phase B: warps 0-7 compute (4 m x 2 n16); all warps stage + sync.
#define RC_WAHI 0
#define RC_WALO 66560
#define RC_WBHI 133120
#define RC_WBLO 166400
#define RC_A    199680          // 3 bufs x (hi 5120 + lo 5120)
#define RC_ABUF 10240
#define RC_SMEM (RC_A + 3*RC_ABUF)   // 230400
__global__ void __launch_bounds__(512, 1) recur_mma(
    const float* __restrict__ seq, const float* __restrict__ state0,
    const float* __restrict__ Wg, const float* __restrict__ bg,
    const float* __restrict__ Wlin, const float* __restrict__ blin)
{
    extern __shared__ char sm[];
    uint32_t smu = smem_u32(sm);
    int tid = threadIdx.x;
    int w = tid >> 5, lane = tid & 31;
    int cta = blockIdx.x;
    int b0 = (cta & 7)*64;
    int j0 = (cta >> 3)*32;

    // stage Wg slab (64 rows: 32 z + 32 r) and Wlin slab (32 rows), split hi/lo
    for (int e = tid; e < 64*KST; e += 512) {
        int n = e >> 9, k = e & (KST-1);
        int grow = (n < 32) ? (j0 + n) : (KST + j0 + n - 32);
        float v = Wg[(size_t)grow*KST + k];
        bf16 h = __float2bfloat16(v);
        size_t o = (size_t)n*BSTR + k;
        ((bf16*)(sm + RC_WAHI))[o] = h;
        ((bf16*)(sm + RC_WALO))[o] = __float2bfloat16(v - __bfloat162float(h));
    }
    for (int e = tid; e < 32*KST; e += 512) {
        int n = e >> 9, k = e & (KST-1);
        float v = Wlin[(size_t)(j0 + n)*KST + k];
        bf16 h = __float2bfloat16(v);
        size_t o = (size_t)n*BSTR + k;
        ((bf16*)(sm + RC_WBHI))[o] = h;
        ((bf16*)(sm + RC_WBLO))[o] = __float2bfloat16(v - __bfloat162float(h));
    }
    // init h + split
    for (int idx = cta*512 + tid; idx < B_SZ*KST; idx += NBR*512) {
        float h0 = state0[idx & (KST-1)];
        g_h[idx] = h0;
        split_store(g_hs_hi, g_hs_lo, idx, h0);
    }
    grid_sync();

    // per-warp geometry
    int mtA = w & 3;                 // 16-row group (both phases)
    int chA = w >> 2;                // phase A: n16 group (0..3) over 64 gate cols
    int coB = ((w >> 2) & 1)*16;     // phase B (w<8): n16 half
    uint32_t a_offA = ((uint32_t)(16*mtA + (lane & 15))*ASTR + ((lane >> 4) << 3)) * 2;
    uint32_t b_row = (lane & 7) + ((lane & 16) >> 1);
    uint32_t b_k8  = (lane & 8);

    // A staging: 64 rows x 32 k; threads 0-255 hi, 256-511 lo; 1 cp16 each
    int arr  = tid >> 8;
    int srow = (tid & 255) >> 2, skc = (tid & 3)*8;
    uint32_t sdst = (uint32_t)(srow*ASTR + skc)*2 + (uint32_t)arr*5120;
    const size_t arow_off = (size_t)(b0 + srow)*KST + skc;

    #pragma unroll 1
    for (int t = 0; t < L_SEQ; ++t) {
        const float* Lxt = g_Lx + (size_t)t*B_SZ*NLX;
        #pragma unroll 1
        for (int s = 1; s <= 4; ++s) {
            const float* hin = (s==1) ? g_h : (s==2 ? g_hA : (s==3 ? g_hB : g_hA));

            // ================= phase A: gate GEMM (z,r) =================
            {
                float acc[2][4];
                acc[0][0]=0.f; acc[0][1]=0.f; acc[0][2]=0.f; acc[0][3]=0.f;
                acc[1][0]=0.f; acc[1][1]=0.f; acc[1][2]=0.f; acc[1][3]=0.f;
                const bf16* sp = (arr ? g_hs_lo : g_hs_hi) + arow_off;
                {
                    cp16(smu + RC_A + sdst, sp);
                    CP_COMMIT();
                }
                #pragma unroll 1
                for (int c = 0; c < 16; c++) {
                    if (c + 1 < 16) {
                        cp16(smu + RC_A + ((c+1)%3)*RC_ABUF + sdst, sp + (c+1)*32);
                        CP_COMMIT();
                        CP_WAIT(1);
                    } else {
                        CP_WAIT(0);
                    }
                    __syncthreads();
                    uint32_t abase = smu + RC_A + (c%3)*RC_ABUF;
                    #pragma unroll
                    for (int ks = 0; ks < 2; ks++) {
                        uint32_t ah[4], al[4];
                        ldsm4(ah, abase + a_offA + ks*32);
                        ldsm4(al, abase + 5120 + a_offA + ks*32);
                        uint32_t kb = (uint32_t)(c*32 + ks*16 + b_k8)*2;
                        uint32_t bh[4], bl[4];
                        uint32_t bo = (uint32_t)(16*chA + b_row)*BSTR*2 + kb;
                        ldsm4(bh, smu + RC_WAHI + bo);
                        ldsm4(bl, smu + RC_WALO + bo);
                        mma16816(acc[0], ah, bh[0], bh[1]);
                        mma16816(acc[1], ah, bh[2], bh[3]);
                        mma16816(acc[0], ah, bl[0], bl[1]);
                        mma16816(acc[1], ah, bl[2], bl[3]);
                        mma16816(acc[0], al, bh[0], bh[1]);
                        mma16816(acc[1], al, bh[2], bh[3]);
                    }
                }
                // gate epilogue: warp covers rows [b0+16mtA,+16), gate cols [16chA,+16)
                int rowl = b0 + 16*mtA + (lane >> 2);
                #pragma unroll
                for (int nt = 0; nt < 2; nt++) {
                    int gcb = 16*chA + 8*nt + 2*(lane & 3);
                    #pragma unroll
                    for (int rr = 0; rr < 2; rr++) {
                        int row = rowl + 8*rr;
                        const float* lx = Lxt + (size_t)row*NLX;
                        #pragma unroll
                        for (int jj = 0; jj < 2; jj++) {
                            int gc = gcb + jj;
                            float a = acc[nt][2*rr + jj];
                            if (chA < 2) {
                                int j = j0 + gc;
                                g_zg[(size_t)row*KST + j] = fsigmoid(a + lx[j] + bg[j]);
                            } else {
                                int j = j0 + gc - 32;
                                size_t idx = (size_t)row*KST + j;
                                float r = fsigmoid(a + lx[KST + j] + bg[KST + j]);
                                split_store(g_us_hi, g_us_lo, idx, r * hin[idx]);
                            }
                        }
                    }
                }
            }
            grid_sync();

            // ================= phase B: lin GEMM + RK4 =================
            {
                float acc[2][4];
                acc[0][0]=0.f; acc[0][1]=0.f; acc[0][2]=0.f; acc[0][3]=0.f;
                acc[1][0]=0.f; acc[1][1]=0.f; acc[1][2]=0.f; acc[1][3]=0.f;
                const bf16* sp = (arr ? g_us_lo : g_us_hi) + arow_off;
                {
                    cp16(smu + RC_A + sdst, sp);
                    CP_COMMIT();
                }
                #pragma unroll 1
                for (int c = 0; c < 16; c++) {
                    if (c + 1 < 16) {
                        cp16(smu + RC_A + ((c+1)%3)*RC_ABUF + sdst, sp + (c+1)*32);
                        CP_COMMIT();
                        CP_WAIT(1);
                    } else {
                        CP_WAIT(0);
                    }
                    __syncthreads();
                    if (w < 8) {
                        uint32_t abase = smu + RC_A + (c%3)*RC_ABUF;
                        #pragma unroll
                        for (int ks = 0; ks < 2; ks++) {
                            uint32_t ah[4], al[4];
                            ldsm4(ah, abase + a_offA + ks*32);
                            ldsm4(al, abase + 5120 + a_offA + ks*32);
                            uint32_t kb = (uint32_t)(c*32 + ks*16 + b_k8)*2;
                            uint32_t bh[4], bl[4];
                            uint32_t bo = (uint32_t)(coB + b_row)*BSTR*2 + kb;
                            ldsm4(bh, smu + RC_WBHI + bo);
                            ldsm4(bl, smu + RC_WBLO + bo);
                            mma16816(acc[0], ah, bh[0], bh[1]);
                            mma16816(acc[1], ah, bh[2], bh[3]);
                            mma16816(acc[0], ah, bl[0], bl[1]);
                            mma16816(acc[1], ah, bl[2], bl[3]);
                            mma16816(acc[0], al, bh[0], bh[1]);
                            mma16816(acc[1], al, bh[2], bh[3]);
                        }
                    }
                }
                // RK4 epilogue (warps 0-7 only)
                if (w < 8) {
                    int rowl = b0 + 16*mtA + (lane >> 2);
                    #pragma unroll
                    for (int rr = 0; rr < 2; rr++) {
                        int row = rowl + 8*rr;
                        float dt = (t > 0) ? seq[((size_t)(t-1)*B_SZ + row)*16 + 15] : 0.f;
                        const float* lx = Lxt + (size_t)row*NLX;
                        #pragma unroll
                        for (int nt = 0; nt < 2; nt++) {
                            int jl = coB + 8*nt + 2*(lane & 3);
                            #pragma unroll
                            for (int jj = 0; jj < 2; jj++) {
                                int j = j0 + jl + jj;
                                size_t idx = (size_t)row*KST + j;
                                float hv = hin[idx];
                                float kv = g_zg[idx] * (ftanh(acc[nt][2*rr + jj] + lx[2*KST + j] + blin[j]) - hv);
                                float ht;
                                if (s == 1)      { g_acc[idx]  = kv;      ht = g_h[idx] + dt*0.5f*kv; g_hA[idx] = ht; }
                                else if (s == 2) { g_acc[idx] += 2.f*kv;  ht = g_h[idx] + dt*0.5f*kv; g_hB[idx] = ht; }
                                else if (s == 3) { g_acc[idx] += 2.f*kv;  ht = g_h[idx] + dt*kv;      g_hA[idx] = ht; }
                                else {
                                    ht = g_h[idx] + dt*(g_acc[idx] + kv)*(1.f/6.f);
                                    g_h[idx] = ht;
                                    split_store(g_st_hi, g_st_lo, (size_t)t*B_SZ*KST + idx, ht);
                                }
                                split_store(g_hs_hi, g_hs_lo, idx, ht);
                            }
                        }
                    }
                }
            }
            grid_sync();
        }
    }
}

// ---------------- out[1..255] = g_ty @ Ly2^T ----------------
__global__ void yout_kernel(const float* __restrict__ Ly2, float* __restrict__ out) {
    __shared__ float l2s[8*KST];
    int tid = threadIdx.x;
    for (int i = tid; i < 8*KST; i += 256) l2s[i] = Ly2[i];
    __syncthreads();
    int warp = tid >> 5, lane = tid & 31;
    int tok = blockIdx.x*8 + warp;
    const float* tr = g_ty + (size_t)tok*KST;
    float p[8] = {};
    for (int k = lane; k < KST; k += 32) {
        float tv = tr[k];
        #pragma unroll
        for (int o = 0; o < 8; o++) p[o] += tv*l2s[o*KST + k];
    }
    #pragma unroll
    for (int o = 0; o < 8; o++)
        #pragma unroll
        for (int off = 16; off; off >>= 1)
            p[o] += __shfl_xor_sync(0xffffffffu, p[o], off);
    if (lane == 0) {
        float* op = out + (size_t)(tok + B_SZ)*8;
        #pragma unroll
        for (int o = 0; o < 8; o++) op[o] = p[o];
    }
}

// ---------------- out[0] = Ly(h0) broadcast over batch ----------------
__global__ void y0_kernel(const float* __restrict__ state0,
                          const float* __restrict__ Ly1,
                          const float* __restrict__ Ly2,
                          float* __restrict__ out) {
    __shared__ float h0s[KST];
    __shared__ float tys[KST];
    __shared__ float y0s[8];
    int tid = threadIdx.x;
    for (int j = tid; j < KST; j += 256) h0s[j] = state0[j];
    __syncthreads();
    for (int j = tid; j < KST; j += 256) {
        float s = 0.f;
        const float* lr = Ly1 + (size_t)j*KST;
        for (int k = 0; k < KST; k++) s += h0s[k]*lr[k];
        tys[j] = tanhf(s);
    }
    __syncthreads();
    if (tid < 8) {
        float s = 0.f;
        const float* lr = Ly2 + (size_t)tid*KST;
        for (int k = 0; k < KST; k++) s += tys[k]*lr[k];
        y0s[tid] = s;
    }
    __syncthreads();
    for (int i = tid; i < B_SZ*8; i += 256) out[i] = y0s[i & 7];
}

// ---------------- launch ----------------
extern "C" void kernel_launch(void* const* d_in, const int* in_sizes, int n_in,
                              void* d_out, int out_size) {
    const float* seq    = (const float*)d_in[0];
    const float* state0 = (const float*)d_in[1];
    const float* Win    = (const float*)d_in[2];
    const float* bin    = (const float*)d_in[3];
    const float* Wx     = (const float*)d_in[4];
    const float* Wg     = (const float*)d_in[5];
    const float* bg     = (const float*)d_in[6];
    const float* Wlin   = (const float*)d_in[7];
    const float* blin   = (const float*)d_in[8];
    const float* Ly1    = (const float*)d_in[9];
    const float* Ly2    = (const float*)d_in[10];
    float* out = (float*)d_out;

    bf16 *xeh, *xel, *sth, *stl;
    float *Lx, *ty;
    cudaGetSymbolAddress((void**)&xeh, g_xe_hi);
    cudaGetSymbolAddress((void**)&xel, g_xe_lo);
    cudaGetSymbolAddress((void**)&sth, g_st_hi);
    cudaGetSymbolAddress((void**)&stl, g_st_lo);
    cudaGetSymbolAddress((void**)&Lx,  g_Lx);
    cudaGetSymbolAddress((void**)&ty,  g_ty);

    cudaFuncSetAttribute(recur_mma, cudaFuncAttributeMaxDynamicSharedMemorySize, RC_SMEM);
    cudaFuncSetAttribute(gemm_split<0>, cudaFuncAttributeMaxDynamicSharedMemorySize, GS_SMEM);
    cudaFuncSetAttribute(gemm_split<1>, cudaFuncAttributeMaxDynamicSharedMemorySize, GS_SMEM);

    embed_kernel<<<NTOK, 128>>>(seq, Win, bin);
    gemm_split<0><<<dim3(NTOK/128, NLX/64), 512, GS_SMEM>>>(xeh, xel, Wx, Lx, NLX);

    recur_mma<<<NBR, 512, RC_SMEM>>>(seq, state0, Wg, bg, Wlin, blin);

    gemm_split<1><<<dim3((NTOK - B_SZ)/128, KST/64), 512, GS_SMEM>>>(sth, stl, Ly1, ty, KST);
    yout_kernel<<<(NTOK - B_SZ)/8, 256>>>(Ly2, out);
    y0_kernel<<<1, 256>>>(state0, Ly1, Ly2, out);
}

// round 11
// speedup vs baseline: 1.0158x; 1.0158x over previous
#include <cuda_runtime.h>
#include <cuda_bf16.h>
#include <math.h>
#include <stdint.h>

#define L_SEQ 256
#define B_SZ  512
#define KIN   15
#define KST   512
#define NLX   1536
#define NTOK  (L_SEQ*B_SZ)   // 131072
#define NBR   128            // persistent CTAs for recurrence
#define BSTR  520            // weight-slab row stride (bf16 elems), 1040B rows
#define ASTR  40             // A-chunk row stride (bf16 elems) for gemm_split staging

typedef unsigned long long ull;
typedef __nv_bfloat16 bf16;

// ---------------- scratch (device globals; no allocation) ----------------
__device__ __align__(16) bf16 g_xe_hi[(size_t)NTOK*KST];
__device__ __align__(16) bf16 g_xe_lo[(size_t)NTOK*KST];
__device__ float g_Lx[(size_t)NTOK*NLX];
__device__ __align__(16) bf16 g_st_hi[(size_t)NTOK*KST];
__device__ __align__(16) bf16 g_st_lo[(size_t)NTOK*KST];
__device__ float g_ty[(size_t)(NTOK-B_SZ)*KST];
__device__ float g_h  [B_SZ*KST];
__device__ float g_hA [B_SZ*KST];
__device__ float g_hB [B_SZ*KST];
__device__ float g_acc[B_SZ*KST];
__device__ float g_zg [B_SZ*KST];
__device__ __align__(16) bf16 g_hs_hi[B_SZ*KST];
__device__ __align__(16) bf16 g_hs_lo[B_SZ*KST];
__device__ __align__(16) bf16 g_us_hi[B_SZ*KST];
__device__ __align__(16) bf16 g_us_lo[B_SZ*KST];
__device__ unsigned g_bar_count = 0;
__device__ volatile unsigned g_bar_gen = 0;

// fast activations (MUFU-based, ~1e-6 rel err, saturating at +-inf)
__device__ __forceinline__ float fsigmoid(float x) { return 1.f/(1.f + __expf(-x)); }
__device__ __forceinline__ float ftanh(float x) {
    float e = __expf(2.f*x);
    return 1.f - __fdividef(2.f, e + 1.f);
}

// ---------------- warp-MMA + async-copy primitives (sm_80+ baseline PTX) ----------------
__device__ __forceinline__ uint32_t smem_u32(const void* p) {
    uint32_t a;
    asm("{ .reg .u64 t; cvta.to.shared.u64 t, %1; cvt.u32.u64 %0, t; }" : "=r"(a) : "l"(p));
    return a;
}
__device__ __forceinline__ void ldsm4(uint32_t* r, uint32_t addr) {
    asm volatile("ldmatrix.sync.aligned.m8n8.x4.shared.b16 {%0,%1,%2,%3}, [%4];"
        : "=r"(r[0]), "=r"(r[1]), "=r"(r[2]), "=r"(r[3]) : "r"(addr));
}
__device__ __forceinline__ void mma16816(float* d, const uint32_t* a, uint32_t b0, uint32_t b1) {
    asm volatile("mma.sync.aligned.m16n8k16.row.col.f32.bf16.bf16.f32 "
        "{%0,%1,%2,%3}, {%4,%5,%6,%7}, {%8,%9}, {%0,%1,%2,%3};"
        : "+f"(d[0]), "+f"(d[1]), "+f"(d[2]), "+f"(d[3])
        : "r"(a[0]), "r"(a[1]), "r"(a[2]), "r"(a[3]), "r"(b0), "r"(b1));
}
__device__ __forceinline__ void cp16(uint32_t dst, const void* src) {
    asm volatile("cp.async.cg.shared.global [%0], [%1], 16;" :: "r"(dst), "l"(src));
}
#define CP_COMMIT() asm volatile("cp.async.commit_group;" ::: "memory")
#define CP_WAIT(n)  asm volatile("cp.async.wait_group %0;" :: "n"(n) : "memory")

__device__ __forceinline__ void split_store(bf16* hi, bf16* lo, size_t idx, float v) {
    bf16 h = __float2bfloat16(v);
    hi[idx] = h;
    lo[idx] = __float2bfloat16(v - __bfloat162float(h));
}

// software grid barrier across NBR CTAs (all resident: 1 CTA/SM via smem)
__device__ __forceinline__ void grid_sync() {
    __syncthreads();
    if (threadIdx.x == 0) {
        __threadfence();
        unsigned g = g_bar_gen;
        if (atomicAdd(&g_bar_count, 1u) == (unsigned)(NBR - 1)) {
            g_bar_count = 0;
            __threadfence();
            g_bar_gen = g + 1u;
        } else {
            while (g_bar_gen == g) { __nanosleep(40); }
            __threadfence();
        }
    }
    __syncthreads();
}

// ---------------- xe = tanh(x @ Win^T + bin), split to bf16 hi/lo ----------------
__global__ void embed_kernel(const float* __restrict__ seq,
                             const float* __restrict__ Win,
                             const float* __restrict__ bin) {
    int tok = blockIdx.x;
    __shared__ float xs[KIN];
    if (threadIdx.x < KIN) xs[threadIdx.x] = seq[(size_t)tok*16 + threadIdx.x];
    __syncthreads();
    for (int j = threadIdx.x; j < KST; j += blockDim.x) {
        float s = bin[j];
        const float* wr = Win + j*KIN;
        #pragma unroll
        for (int i = 0; i < KIN; i++) s += xs[i]*wr[i];
        split_store(g_xe_hi, g_xe_lo, (size_t)tok*KST + j, ftanh(s));
    }
}

// ---------------- split-bf16 GEMM: C = act(A @ B^T), tile 128x64, K=512 ----------------
// cp.async 3-stage pipelined A chunks (k=32); B slab staged once. (R9 config: 256 thr)
#define GS_WHI  0
#define GS_WLO  66560
#define GS_A    133120          // 3 bufs x (hi 10240 + lo 10240)
#define GS_ABUF 20480
#define GS_SMEM (GS_A + 3*GS_ABUF)   // 194560
template<int TANH>
__global__ void __launch_bounds__(256) gemm_split(
    const bf16* __restrict__ Ahi, const bf16* __restrict__ Alo,
    const float* __restrict__ B, float* __restrict__ C, int N)
{
    extern __shared__ char sm[];
    uint32_t smu = smem_u32(sm);
    int tid = threadIdx.x;
    int w = tid >> 5, lane = tid & 31;
    int bm = blockIdx.x*128, bn = blockIdx.y*64;

    // stage B slab: 64 rows x 512 k, split fp32 -> hi/lo bf16
    for (int e = tid; e < 64*KST; e += 256) {
        int n = e >> 9, k = e & (KST-1);
        float v = B[(size_t)(bn + n)*KST + k];
        bf16 h = __float2bfloat16(v);
        size_t o = (size_t)n*BSTR + k;
        ((bf16*)(sm + GS_WHI))[o] = h;
        ((bf16*)(sm + GS_WLO))[o] = __float2bfloat16(v - __bfloat162float(h));
    }

    float acc[8][4];
    #pragma unroll
    for (int i = 0; i < 8; i++) { acc[i][0]=0.f; acc[i][1]=0.f; acc[i][2]=0.f; acc[i][3]=0.f; }

    uint32_t a_off = ((uint32_t)(16*w + (lane & 15))*ASTR + ((lane >> 4) << 3)) * 2;
    uint32_t b_row = (lane & 7) + ((lane & 16) >> 1);
    uint32_t b_k8  = (lane & 8);

    // A staging: 128 rows x 32 k, 2 thr/row, each 16 elems via 2x cp16 per array
    int srow = tid >> 1, skc = (tid & 1)*16;
    const bf16* ahp = Ahi + (size_t)(bm + srow)*KST + skc;
    const bf16* alp = Alo + (size_t)(bm + srow)*KST + skc;
    uint32_t sdst = (uint32_t)(srow*ASTR + skc)*2;

    // prologue: chunk 0
    {
        uint32_t d = smu + GS_A + sdst;
        cp16(d,      ahp);      cp16(d + 16,      ahp + 8);
        cp16(d + 10240, alp);   cp16(d + 10240 + 16, alp + 8);
        CP_COMMIT();
    }
    __syncthreads();   // B slab visible

    #pragma unroll 1
    for (int c = 0; c < 16; c++) {
        if (c + 1 < 16) {
            uint32_t d = smu + GS_A + ((c+1)%3)*GS_ABUF + sdst;
            const bf16* ah = ahp + (c+1)*32;
            const bf16* al = alp + (c+1)*32;
            cp16(d, ah);          cp16(d + 16, ah + 8);
            cp16(d + 10240, al);  cp16(d + 10240 + 16, al + 8);
            CP_COMMIT();
            CP_WAIT(1);
        } else {
            CP_WAIT(0);
        }
        __syncthreads();
        uint32_t abase = smu + GS_A + (c%3)*GS_ABUF;
        #pragma unroll
        for (int ks = 0; ks < 2; ks++) {
            uint32_t ah[4], al[4];
            ldsm4(ah, abase + a_off + ks*32);
            ldsm4(al, abase + 10240 + a_off + ks*32);
            uint32_t kb = (uint32_t)(c*32 + ks*16 + b_k8)*2;
            #pragma unroll
            for (int p = 0; p < 4; p++) {
                uint32_t bh[4], bl[4];
                uint32_t bo = (uint32_t)(16*p + b_row)*BSTR*2 + kb;
                ldsm4(bh, smu + GS_WHI + bo);
                ldsm4(bl, smu + GS_WLO + bo);
                mma16816(acc[2*p],   ah, bh[0], bh[1]);
                mma16816(acc[2*p+1], ah, bh[2], bh[3]);
                mma16816(acc[2*p],   ah, bl[0], bl[1]);
                mma16816(acc[2*p+1], ah, bl[2], bl[3]);
                mma16816(acc[2*p],   al, bh[0], bh[1]);
                mma16816(acc[2*p+1], al, bh[2], bh[3]);
            }
        }
    }

    int rowl = bm + 16*w + (lane >> 2);
    #pragma unroll
    for (int nt = 0; nt < 8; nt++) {
        int col = bn + 8*nt + 2*(lane & 3);
        #pragma unroll
        for (int rr = 0; rr < 2; rr++) {
            size_t ro = (size_t)(rowl + 8*rr)*N + col;
            float v0 = acc[nt][2*rr], v1 = acc[nt][2*rr+1];
            if (TANH) { v0 = ftanh(v0); v1 = ftanh(v1); }
            C[ro] = v0; C[ro + 1] = v1;
        }
    }
}

// ---------------- persistent recurrence kernel (warp-MMA, direct-LDG A fragments) ----------------
// 128 CTAs x 256 thr. CTA: b0 = (cta&7)*64 rows, j0 = (cta>>3)*32 state cols.
// A fragments loaded straight from gmem into mma register layout -> ZERO barriers in mainloop.
// B (weights) resident in smem, read via ldmatrix.
#define RC_WAHI 0
#define RC_WALO 66560
#define RC_WBHI 133120
#define RC_WBLO 166400
#define RC_SMEM 199680
__global__ void __launch_bounds__(256, 1) recur_mma(
    const float* __restrict__ seq, const float* __restrict__ state0,
    const float* __restrict__ Wg, const float* __restrict__ bg,
    const float* __restrict__ Wlin, const float* __restrict__ blin)
{
    extern __shared__ char sm[];
    uint32_t smu = smem_u32(sm);
    int tid = threadIdx.x;
    int w = tid >> 5, lane = tid & 31;
    int cta = blockIdx.x;
    int b0 = (cta & 7)*64;
    int j0 = (cta >> 3)*32;

    // stage Wg slab (64 rows: 32 z + 32 r) and Wlin slab (32 rows), split hi/lo
    for (int e = tid; e < 64*KST; e += 256) {
        int n = e >> 9, k = e & (KST-1);
        int grow = (n < 32) ? (j0 + n) : (KST + j0 + n - 32);
        float v = Wg[(size_t)grow*KST + k];
        bf16 h = __float2bfloat16(v);
        size_t o = (size_t)n*BSTR + k;
        ((bf16*)(sm + RC_WAHI))[o] = h;
        ((bf16*)(sm + RC_WALO))[o] = __float2bfloat16(v - __bfloat162float(h));
    }
    for (int e = tid; e < 32*KST; e += 256) {
        int n = e >> 9, k = e & (KST-1);
        float v = Wlin[(size_t)(j0 + n)*KST + k];
        bf16 h = __float2bfloat16(v);
        size_t o = (size_t)n*BSTR + k;
        ((bf16*)(sm + RC_WBHI))[o] = h;
        ((bf16*)(sm + RC_WBLO))[o] = __float2bfloat16(v - __bfloat162float(h));
    }
    // init h + split
    for (int idx = cta*256 + tid; idx < B_SZ*KST; idx += NBR*256) {
        float h0 = state0[idx & (KST-1)];
        g_h[idx] = h0;
        split_store(g_hs_hi, g_hs_lo, idx, h0);
    }
    grid_sync();

    // per-warp geometry: 8 warps = 4 m-tiles x 2 n-halves
    int mtA = w & 3, chA = w >> 2;          // phase A: n-half over 64 gate cols
    int coB = (w >> 2)*16;                  // phase B: n16 half of 32 lin cols
    uint32_t b_row = (lane & 7) + ((lane & 16) >> 1);
    uint32_t b_k8  = (lane & 8);

    // direct A-fragment gmem offsets (this warp's 16 rows)
    const size_t afrag = (size_t)(b0 + 16*mtA + (lane >> 2))*KST + (lane & 3)*2;

    #pragma unroll 1
    for (int t = 0; t < L_SEQ; ++t) {
        const float* Lxt = g_Lx + (size_t)t*B_SZ*NLX;
        #pragma unroll 1
        for (int s = 1; s <= 4; ++s) {
            const float* hin = (s==1) ? g_h : (s==2 ? g_hA : (s==3 ? g_hB : g_hA));

            // ================= phase A: gate GEMM (z,r) — no barriers =================
            {
                float acc[4][4];
                #pragma unroll
                for (int i = 0; i < 4; i++) { acc[i][0]=0.f; acc[i][1]=0.f; acc[i][2]=0.f; acc[i][3]=0.f; }
                const bf16* ph = g_hs_hi + afrag;
                const bf16* pl = g_hs_lo + afrag;
                #pragma unroll 4
                for (int c = 0; c < 32; c++) {
                    uint32_t ah[4], al[4];
                    const bf16* phc = ph + c*16;
                    const bf16* plc = pl + c*16;
                    ah[0] = *(const uint32_t*)(phc);
                    ah[1] = *(const uint32_t*)(phc + 8*KST);
                    ah[2] = *(const uint32_t*)(phc + 8);
                    ah[3] = *(const uint32_t*)(phc + 8*KST + 8);
                    al[0] = *(const uint32_t*)(plc);
                    al[1] = *(const uint32_t*)(plc + 8*KST);
                    al[2] = *(const uint32_t*)(plc + 8);
                    al[3] = *(const uint32_t*)(plc + 8*KST + 8);
                    uint32_t kb = (uint32_t)(c*16 + b_k8)*2;
                    #pragma unroll
                    for (int p = 0; p < 2; p++) {
                        uint32_t bh[4], bl[4];
                        uint32_t bo = (uint32_t)(32*chA + 16*p + b_row)*BSTR*2 + kb;
                        ldsm4(bh, smu + RC_WAHI + bo);
                        ldsm4(bl, smu + RC_WALO + bo);
                        mma16816(acc[2*p],   ah, bh[0], bh[1]);
                        mma16816(acc[2*p+1], ah, bh[2], bh[3]);
                        mma16816(acc[2*p],   ah, bl[0], bl[1]);
                        mma16816(acc[2*p+1], ah, bl[2], bl[3]);
                        mma16816(acc[2*p],   al, bh[0], bh[1]);
                        mma16816(acc[2*p+1], al, bh[2], bh[3]);
                    }
                }
                // gate epilogue: warp covers rows [b0+16mtA,+16), gate cols [32chA,+32)
                int rowl = b0 + 16*mtA + (lane >> 2);
                #pragma unroll
                for (int nt = 0; nt < 4; nt++) {
                    int gc0 = 32*chA + 8*nt + 2*(lane & 3);
                    #pragma unroll
                    for (int rr = 0; rr < 2; rr++) {
                        int row = rowl + 8*rr;
                        const float* lx = Lxt + (size_t)row*NLX;
                        #pragma unroll
                        for (int jj = 0; jj < 2; jj++) {
                            int gc = gc0 + jj;
                            float a = acc[nt][2*rr + jj];
                            if (chA == 0) {
                                int j = j0 + gc;
                                g_zg[(size_t)row*KST + j] = fsigmoid(a + lx[j] + bg[j]);
                            } else {
                                int j = j0 + gc - 32;
                                size_t idx = (size_t)row*KST + j;
                                float r = fsigmoid(a + lx[KST + j] + bg[KST + j]);
                                split_store(g_us_hi, g_us_lo, idx, r * hin[idx]);
                            }
                        }
                    }
                }
            }
            grid_sync();

            // ================= phase B: lin GEMM + RK4 — no barriers =================
            {
                float acc[2][4];
                acc[0][0]=0.f; acc[0][1]=0.f; acc[0][2]=0.f; acc[0][3]=0.f;
                acc[1][0]=0.f; acc[1][1]=0.f; acc[1][2]=0.f; acc[1][3]=0.f;
                const bf16* ph = g_us_hi + afrag;
                const bf16* pl = g_us_lo + afrag;
                #pragma unroll 4
                for (int c = 0; c < 32; c++) {
                    uint32_t ah[4], al[4];
                    const bf16* phc = ph + c*16;
                    const bf16* plc = pl + c*16;
                    ah[0] = *(const uint32_t*)(phc);
                    ah[1] = *(const uint32_t*)(phc + 8*KST);
                    ah[2] = *(const uint32_t*)(phc + 8);
                    ah[3] = *(const uint32_t*)(phc + 8*KST + 8);
                    al[0] = *(const uint32_t*)(plc);
                    al[1] = *(const uint32_t*)(plc + 8*KST);
                    al[2] = *(const uint32_t*)(plc + 8);
                    al[3] = *(const uint32_t*)(plc + 8*KST + 8);
                    uint32_t kb = (uint32_t)(c*16 + b_k8)*2;
                    uint32_t bh[4], bl[4];
                    uint32_t bo = (uint32_t)(coB + b_row)*BSTR*2 + kb;
                    ldsm4(bh, smu + RC_WBHI + bo);
                    ldsm4(bl, smu + RC_WBLO + bo);
                    mma16816(acc[0], ah, bh[0], bh[1]);
                    mma16816(acc[1], ah, bh[2], bh[3]);
                    mma16816(acc[0], ah, bl[0], bl[1]);
                    mma16816(acc[1], ah, bl[2], bl[3]);
                    mma16816(acc[0], al, bh[0], bh[1]);
                    mma16816(acc[1], al, bh[2], bh[3]);
                }
                // RK4 epilogue: warp covers rows [b0+16mtA,+16), lin cols [coB,+16)
                int rowl = b0 + 16*mtA + (lane >> 2);
                #pragma unroll
                for (int rr = 0; rr < 2; rr++) {
                    int row = rowl + 8*rr;
                    float dt = (t > 0) ? seq[((size_t)(t-1)*B_SZ + row)*16 + 15] : 0.f;
                    const float* lx = Lxt + (size_t)row*NLX;
                    #pragma unroll
                    for (int nt = 0; nt < 2; nt++) {
                        int jl = coB + 8*nt + 2*(lane & 3);
                        #pragma unroll
                        for (int jj = 0; jj < 2; jj++) {
                            int j = j0 + jl + jj;
                            size_t idx = (size_t)row*KST + j;
                            float hv = hin[idx];
                            float kv = g_zg[idx] * (ftanh(acc[nt][2*rr + jj] + lx[2*KST + j] + blin[j]) - hv);
                            float ht;
                            if (s == 1)      { g_acc[idx]  = kv;      ht = g_h[idx] + dt*0.5f*kv; g_hA[idx] = ht; }
                            else if (s == 2) { g_acc[idx] += 2.f*kv;  ht = g_h[idx] + dt*0.5f*kv; g_hB[idx] = ht; }
                            else if (s == 3) { g_acc[idx] += 2.f*kv;  ht = g_h[idx] + dt*kv;      g_hA[idx] = ht; }
                            else {
                                ht = g_h[idx] + dt*(g_acc[idx] + kv)*(1.f/6.f);
                                g_h[idx] = ht;
                                split_store(g_st_hi, g_st_lo, (size_t)t*B_SZ*KST + idx, ht);
                            }
                            split_store(g_hs_hi, g_hs_lo, idx, ht);
                        }
                    }
                }
            }
            grid_sync();
        }
    }
}

// ---------------- out[1..255] = g_ty @ Ly2^T ----------------
__global__ void yout_kernel(const float* __restrict__ Ly2, float* __restrict__ out) {
    __shared__ float l2s[8*KST];
    int tid = threadIdx.x;
    for (int i = tid; i < 8*KST; i += 256) l2s[i] = Ly2[i];
    __syncthreads();
    int warp = tid >> 5, lane = tid & 31;
    int tok = blockIdx.x*8 + warp;
    const float* tr = g_ty + (size_t)tok*KST;
    float p[8] = {};
    for (int k = lane; k < KST; k += 32) {
        float tv = tr[k];
        #pragma unroll
        for (int o = 0; o < 8; o++) p[o] += tv*l2s[o*KST + k];
    }
    #pragma unroll
    for (int o = 0; o < 8; o++)
        #pragma unroll
        for (int off = 16; off; off >>= 1)
            p[o] += __shfl_xor_sync(0xffffffffu, p[o], off);
    if (lane == 0) {
        float* op = out + (size_t)(tok + B_SZ)*8;
        #pragma unroll
        for (int o = 0; o < 8; o++) op[o] = p[o];
    }
}

// ---------------- out[0] = Ly(h0) broadcast over batch ----------------
__global__ void y0_kernel(const float* __restrict__ state0,
                          const float* __restrict__ Ly1,
                          const float* __restrict__ Ly2,
                          float* __restrict__ out) {
    __shared__ float h0s[KST];
    __shared__ float tys[KST];
    __shared__ float y0s[8];
    int tid = threadIdx.x;
    for (int j = tid; j < KST; j += 256) h0s[j] = state0[j];
    __syncthreads();
    for (int j = tid; j < KST; j += 256) {
        float s = 0.f;
        const float* lr = Ly1 + (size_t)j*KST;
        for (int k = 0; k < KST; k++) s += h0s[k]*lr[k];
        tys[j] = tanhf(s);
    }
    __syncthreads();
    if (tid < 8) {
        float s = 0.f;
        const float* lr = Ly2 + (size_t)tid*KST;
        for (int k = 0; k < KST; k++) s += tys[k]*lr[k];
        y0s[tid] = s;
    }
    __syncthreads();
    for (int i = tid; i < B_SZ*8; i += 256) out[i] = y0s[i & 7];
}

// ---------------- launch ----------------
extern "C" void kernel_launch(void* const* d_in, const int* in_sizes, int n_in,
                              void* d_out, int out_size) {
    const float* seq    = (const float*)d_in[0];
    const float* state0 = (const float*)d_in[1];
    const float* Win    = (const float*)d_in[2];
    const float* bin    = (const float*)d_in[3];
    const float* Wx     = (const float*)d_in[4];
    const float* Wg     = (const float*)d_in[5];
    const float* bg     = (const float*)d_in[6];
    const float* Wlin   = (const float*)d_in[7];
    const float* blin   = (const float*)d_in[8];
    const float* Ly1    = (const float*)d_in[9];
    const float* Ly2    = (const float*)d_in[10];
    float* out = (float*)d_out;

    bf16 *xeh, *xel, *sth, *stl;
    float *Lx, *ty;
    cudaGetSymbolAddress((void**)&xeh, g_xe_hi);
    cudaGetSymbolAddress((void**)&xel, g_xe_lo);
    cudaGetSymbolAddress((void**)&sth, g_st_hi);
    cudaGetSymbolAddress((void**)&stl, g_st_lo);
    cudaGetSymbolAddress((void**)&Lx,  g_Lx);
    cudaGetSymbolAddress((void**)&ty,  g_ty);

    cudaFuncSetAttribute(recur_mma, cudaFuncAttributeMaxDynamicSharedMemorySize, RC_SMEM);
    cudaFuncSetAttribute(gemm_split<0>, cudaFuncAttributeMaxDynamicSharedMemorySize, GS_SMEM);
    cudaFuncSetAttribute(gemm_split<1>, cudaFuncAttributeMaxDynamicSharedMemorySize, GS_SMEM);

    embed_kernel<<<NTOK, 128>>>(seq, Win, bin);
    gemm_split<0><<<dim3(NTOK/128, NLX/64), 256, GS_SMEM>>>(xeh, xel, Wx, Lx, NLX);

    recur_mma<<<NBR, 256, RC_SMEM>>>(seq, state0, Wg, bg, Wlin, blin);

    gemm_split<1><<<dim3((NTOK - B_SZ)/128, KST/64), 256, GS_SMEM>>>(sth, stl, Ly1, ty, KST);
    yout_kernel<<<(NTOK - B_SZ)/8, 256>>>(Ly2, out);
    y0_kernel<<<1, 256>>>(state0, Ly1, Ly2, out);
}

// round 14
// speedup vs baseline: 1.2320x; 1.2128x over previous
#include <cuda_runtime.h>
#include <cuda_bf16.h>
#include <math.h>
#include <stdint.h>

#define L_SEQ 256
#define B_SZ  512
#define KIN   15
#define KST   512
#define NLX   1536
#define NTOK  (L_SEQ*B_SZ)   // 131072
#define NBR   128            // persistent CTAs for recurrence
#define BSTR  520            // weight-slab row stride (bf16 elems), 1040B rows
#define ASTR  40             // A-chunk row stride (bf16 elems)

typedef unsigned long long ull;
typedef __nv_bfloat16 bf16;

// ---------------- scratch (device globals; no allocation) ----------------
__device__ __align__(16) bf16 g_xe_hi[(size_t)NTOK*KST];
__device__ __align__(16) bf16 g_xe_lo[(size_t)NTOK*KST];
__device__ float g_Lx[(size_t)NTOK*NLX];
__device__ __align__(16) bf16 g_st_hi[(size_t)NTOK*KST];
__device__ __align__(16) bf16 g_st_lo[(size_t)NTOK*KST];
__device__ float g_ty[(size_t)(NTOK-B_SZ)*KST];
__device__ float g_h  [B_SZ*KST];
__device__ float g_hA [B_SZ*KST];
__device__ float g_hB [B_SZ*KST];
__device__ float g_acc[B_SZ*KST];
__device__ float g_zg [B_SZ*KST];
__device__ __align__(16) bf16 g_hs_hi[B_SZ*KST];
__device__ __align__(16) bf16 g_hs_lo[B_SZ*KST];
__device__ __align__(16) bf16 g_us_hi[B_SZ*KST];
__device__ __align__(16) bf16 g_us_lo[B_SZ*KST];
__device__ unsigned g_bar_count = 0;
__device__ volatile unsigned g_bar_gen = 0;

// fast activations (MUFU-based, ~1e-6 rel err, saturating at +-inf)
__device__ __forceinline__ float fsigmoid(float x) { return 1.f/(1.f + __expf(-x)); }
__device__ __forceinline__ float ftanh(float x) {
    float e = __expf(2.f*x);
    return 1.f - __fdividef(2.f, e + 1.f);
}

// ---------------- warp-MMA + async-copy primitives (sm_80+ baseline PTX) ----------------
__device__ __forceinline__ uint32_t smem_u32(const void* p) {
    uint32_t a;
    asm("{ .reg .u64 t; cvta.to.shared.u64 t, %1; cvt.u32.u64 %0, t; }" : "=r"(a) : "l"(p));
    return a;
}
__device__ __forceinline__ void ldsm4(uint32_t* r, uint32_t addr) {
    asm volatile("ldmatrix.sync.aligned.m8n8.x4.shared.b16 {%0,%1,%2,%3}, [%4];"
        : "=r"(r[0]), "=r"(r[1]), "=r"(r[2]), "=r"(r[3]) : "r"(addr));
}
__device__ __forceinline__ void mma16816(float* d, const uint32_t* a, uint32_t b0, uint32_t b1) {
    asm volatile("mma.sync.aligned.m16n8k16.row.col.f32.bf16.bf16.f32 "
        "{%0,%1,%2,%3}, {%4,%5,%6,%7}, {%8,%9}, {%0,%1,%2,%3};"
        : "+f"(d[0]), "+f"(d[1]), "+f"(d[2]), "+f"(d[3])
        : "r"(a[0]), "r"(a[1]), "r"(a[2]), "r"(a[3]), "r"(b0), "r"(b1));
}
__device__ __forceinline__ void cp16(uint32_t dst, const void* src) {
    asm volatile("cp.async.cg.shared.global [%0], [%1], 16;" :: "r"(dst), "l"(src));
}
#define CP_COMMIT() asm volatile("cp.async.commit_group;" ::: "memory")
#define CP_WAIT(n)  asm volatile("cp.async.wait_group %0;" :: "n"(n) : "memory")

__device__ __forceinline__ void split_store(bf16* hi, bf16* lo, size_t idx, float v) {
    bf16 h = __float2bfloat16(v);
    hi[idx] = h;
    lo[idx] = __float2bfloat16(v - __bfloat162float(h));
}

// software grid barrier across NBR CTAs (tight spin; all CTAs resident 1/SM)
__device__ __forceinline__ void grid_sync() {
    __syncthreads();
    if (threadIdx.x == 0) {
        __threadfence();
        unsigned g = g_bar_gen;
        if (atomicAdd(&g_bar_count, 1u) == (unsigned)(NBR - 1)) {
            g_bar_count = 0;
            __threadfence();
            g_bar_gen = g + 1u;
        } else {
            while (g_bar_gen == g) { }
            __threadfence();
        }
    }
    __syncthreads();
}

// ---------------- xe = tanh(x @ Win^T + bin), split to bf16 hi/lo ----------------
__global__ void embed_kernel(const float* __restrict__ seq,
                             const float* __restrict__ Win,
                             const float* __restrict__ bin) {
    int tok = blockIdx.x;
    __shared__ float xs[KIN];
    if (threadIdx.x < KIN) xs[threadIdx.x] = seq[(size_t)tok*16 + threadIdx.x];
    __syncthreads();
    for (int j = threadIdx.x; j < KST; j += blockDim.x) {
        float s = bin[j];
        const float* wr = Win + j*KIN;
        #pragma unroll
        for (int i = 0; i < KIN; i++) s += xs[i]*wr[i];
        split_store(g_xe_hi, g_xe_lo, (size_t)tok*KST + j, ftanh(s));
    }
}

// ---------------- split-bf16 GEMM: C = act(A @ B^T), tile 128x64, K=512 ----------------
// cp.async depth-2 pipelined A chunks (k=32, 3 bufs); B slab staged once. 256 thr.
#define GS_WHI  0
#define GS_WLO  66560
#define GS_A    133120
#define GS_ABUF 20480
#define GS_SMEM (GS_A + 3*GS_ABUF)   // 194560
template<int TANH>
__global__ void __launch_bounds__(256) gemm_split(
    const bf16* __restrict__ Ahi, const bf16* __restrict__ Alo,
    const float* __restrict__ B, float* __restrict__ C, int N)
{
    extern __shared__ char sm[];
    uint32_t smu = smem_u32(sm);
    int tid = threadIdx.x;
    int w = tid >> 5, lane = tid & 31;
    int bm = blockIdx.x*128, bn = blockIdx.y*64;

    for (int e = tid; e < 64*KST; e += 256) {
        int n = e >> 9, k = e & (KST-1);
        float v = B[(size_t)(bn + n)*KST + k];
        bf16 h = __float2bfloat16(v);
        size_t o = (size_t)n*BSTR + k;
        ((bf16*)(sm + GS_WHI))[o] = h;
        ((bf16*)(sm + GS_WLO))[o] = __float2bfloat16(v - __bfloat162float(h));
    }

    float acc[8][4];
    #pragma unroll
    for (int i = 0; i < 8; i++) { acc[i][0]=0.f; acc[i][1]=0.f; acc[i][2]=0.f; acc[i][3]=0.f; }

    uint32_t a_off = ((uint32_t)(16*w + (lane & 15))*ASTR + ((lane >> 4) << 3)) * 2;
    uint32_t b_row = (lane & 7) + ((lane & 16) >> 1);
    uint32_t b_k8  = (lane & 8);

    int srow = tid >> 1, skc = (tid & 1)*16;
    const bf16* ahp = Ahi + (size_t)(bm + srow)*KST + skc;
    const bf16* alp = Alo + (size_t)(bm + srow)*KST + skc;
    uint32_t sdst = (uint32_t)(srow*ASTR + skc)*2;

    // prologue: commit chunks 0 and 1 (depth-2)
    #pragma unroll
    for (int c0 = 0; c0 < 2; c0++) {
        uint32_t d = smu + GS_A + c0*GS_ABUF + sdst;
        const bf16* ah = ahp + c0*32;
        const bf16* al = alp + c0*32;
        cp16(d, ah);          cp16(d + 16, ah + 8);
        cp16(d + 10240, al);  cp16(d + 10240 + 16, al + 8);
        CP_COMMIT();
    }
    __syncthreads();   // B slab visible

    #pragma unroll 1
    for (int c = 0; c < 16; c++) {
        if (c < 15) { CP_WAIT(1); } else { CP_WAIT(0); }
        __syncthreads();
        if (c + 2 < 16) {
            uint32_t d = smu + GS_A + ((c+2)%3)*GS_ABUF + sdst;
            const bf16* ah = ahp + (c+2)*32;
            const bf16* al = alp + (c+2)*32;
            cp16(d, ah);          cp16(d + 16, ah + 8);
            cp16(d + 10240, al);  cp16(d + 10240 + 16, al + 8);
            CP_COMMIT();
        }
        uint32_t abase = smu + GS_A + (c%3)*GS_ABUF;
        #pragma unroll
        for (int ks = 0; ks < 2; ks++) {
            uint32_t ah[4], al[4];
            ldsm4(ah, abase + a_off + ks*32);
            ldsm4(al, abase + 10240 + a_off + ks*32);
            uint32_t kb = (uint32_t)(c*32 + ks*16 + b_k8)*2;
            #pragma unroll
            for (int p = 0; p < 4; p++) {
                uint32_t bh[4], bl[4];
                uint32_t bo = (uint32_t)(16*p + b_row)*BSTR*2 + kb;
                ldsm4(bh, smu + GS_WHI + bo);
                ldsm4(bl, smu + GS_WLO + bo);
                mma16816(acc[2*p],   ah, bh[0], bh[1]);
                mma16816(acc[2*p+1], ah, bh[2], bh[3]);
                mma16816(acc[2*p],   ah, bl[0], bl[1]);
                mma16816(acc[2*p+1], ah, bl[2], bl[3]);
                mma16816(acc[2*p],   al, bh[0], bh[1]);
                mma16816(acc[2*p+1], al, bh[2], bh[3]);
            }
        }
    }

    int rowl = bm + 16*w + (lane >> 2);
    #pragma unroll
    for (int nt = 0; nt < 8; nt++) {
        int col = bn + 8*nt + 2*(lane & 3);
        #pragma unroll
        for (int rr = 0; rr < 2; rr++) {
            size_t ro = (size_t)(rowl + 8*rr)*N + col;
            float v0 = acc[nt][2*rr], v1 = acc[nt][2*rr+1];
            if (TANH) { v0 = ftanh(v0); v1 = ftanh(v1); }
            C[ro] = v0; C[ro + 1] = v1;
        }
    }
}

// ---------------- persistent recurrence kernel (R9 structure + depth-2 pipe) ----------------
// 128 CTAs x 256 thr. CTA: b0 = (cta&7)*64 rows, j0 = (cta>>3)*32 state cols.
#define RC_WAHI 0
#define RC_WALO 66560
#define RC_WBHI 133120
#define RC_WBLO 166400
#define RC_A    199680          // 3 bufs x (hi 5120 + lo 5120)
#define RC_ABUF 10240
#define RC_SMEM (RC_A + 3*RC_ABUF)   // 230400
__global__ void __launch_bounds__(256, 1) recur_mma(
    const float* __restrict__ seq, const float* __restrict__ state0,
    const float* __restrict__ Wg, const float* __restrict__ bg,
    const float* __restrict__ Wlin, const float* __restrict__ blin)
{
    extern __shared__ char sm[];
    uint32_t smu = smem_u32(sm);
    int tid = threadIdx.x;
    int w = tid >> 5, lane = tid & 31;
    int cta = blockIdx.x;
    int b0 = (cta & 7)*64;
    int j0 = (cta >> 3)*32;

    // stage Wg slab (64 rows: 32 z + 32 r) and Wlin slab (32 rows), split hi/lo
    for (int e = tid; e < 64*KST; e += 256) {
        int n = e >> 9, k = e & (KST-1);
        int grow = (n < 32) ? (j0 + n) : (KST + j0 + n - 32);
        float v = Wg[(size_t)grow*KST + k];
        bf16 h = __float2bfloat16(v);
        size_t o = (size_t)n*BSTR + k;
        ((bf16*)(sm + RC_WAHI))[o] = h;
        ((bf16*)(sm + RC_WALO))[o] = __float2bfloat16(v - __bfloat162float(h));
    }
    for (int e = tid; e < 32*KST; e += 256) {
        int n = e >> 9, k = e & (KST-1);
        float v = Wlin[(size_t)(j0 + n)*KST + k];
        bf16 h = __float2bfloat16(v);
        size_t o = (size_t)n*BSTR + k;
        ((bf16*)(sm + RC_WBHI))[o] = h;
        ((bf16*)(sm + RC_WBLO))[o] = __float2bfloat16(v - __bfloat162float(h));
    }
    // init h + split
    for (int idx = cta*256 + tid; idx < B_SZ*KST; idx += NBR*256) {
        float h0 = state0[idx & (KST-1)];
        g_h[idx] = h0;
        split_store(g_hs_hi, g_hs_lo, idx, h0);
    }
    grid_sync();

    // per-warp geometry: 8 warps = 4 m-tiles x 2 n-halves
    int mtA = w & 3, chA = w >> 2;
    int coB = (w >> 2)*16;
    uint32_t a_offA = ((uint32_t)(16*mtA + (lane & 15))*ASTR + ((lane >> 4) << 3)) * 2;
    uint32_t b_row = (lane & 7) + ((lane & 16) >> 1);
    uint32_t b_k8  = (lane & 8);

    // A staging: 64 rows x 32 k; 4 thr/row, each 8 elems via 1x cp16 per array
    int srow = tid >> 2, skc = (tid & 3)*8;
    uint32_t sdst = (uint32_t)(srow*ASTR + skc)*2;
    const size_t arow_off = (size_t)(b0 + srow)*KST + skc;

    #pragma unroll 1
    for (int t = 0; t < L_SEQ; ++t) {
        const float* Lxt = g_Lx + (size_t)t*B_SZ*NLX;
        #pragma unroll 1
        for (int s = 1; s <= 4; ++s) {
            const float* hin = (s==1) ? g_h : (s==2 ? g_hA : (s==3 ? g_hB : g_hA));

            // ================= phase A: gate GEMM (z,r) =================
            {
                float acc[4][4];
                #pragma unroll
                for (int i = 0; i < 4; i++) { acc[i][0]=0.f; acc[i][1]=0.f; acc[i][2]=0.f; acc[i][3]=0.f; }
                const bf16* shp = g_hs_hi + arow_off;
                const bf16* slp = g_hs_lo + arow_off;
                #pragma unroll
                for (int c0 = 0; c0 < 2; c0++) {
                    uint32_t d = smu + RC_A + c0*RC_ABUF + sdst;
                    cp16(d,        shp + c0*32);
                    cp16(d + 5120, slp + c0*32);
                    CP_COMMIT();
                }
                #pragma unroll 1
                for (int c = 0; c < 16; c++) {
                    if (c < 15) { CP_WAIT(1); } else { CP_WAIT(0); }
                    __syncthreads();
                    if (c + 2 < 16) {
                        uint32_t d = smu + RC_A + ((c+2)%3)*RC_ABUF + sdst;
                        cp16(d,        shp + (c+2)*32);
                        cp16(d + 5120, slp + (c+2)*32);
                        CP_COMMIT();
                    }
                    uint32_t abase = smu + RC_A + (c%3)*RC_ABUF;
                    #pragma unroll
                    for (int ks = 0; ks < 2; ks++) {
                        uint32_t ah[4], al[4];
                        ldsm4(ah, abase + a_offA + ks*32);
                        ldsm4(al, abase + 5120 + a_offA + ks*32);
                        uint32_t kb = (uint32_t)(c*32 + ks*16 + b_k8)*2;
                        #pragma unroll
                        for (int p = 0; p < 2; p++) {
                            uint32_t bh[4], bl[4];
                            uint32_t bo = (uint32_t)(32*chA + 16*p + b_row)*BSTR*2 + kb;
                            ldsm4(bh, smu + RC_WAHI + bo);
                            ldsm4(bl, smu + RC_WALO + bo);
                            mma16816(acc[2*p],   ah, bh[0], bh[1]);
                            mma16816(acc[2*p+1], ah, bh[2], bh[3]);
                            mma16816(acc[2*p],   ah, bl[0], bl[1]);
                            mma16816(acc[2*p+1], ah, bl[2], bl[3]);
                            mma16816(acc[2*p],   al, bh[0], bh[1]);
                            mma16816(acc[2*p+1], al, bh[2], bh[3]);
                        }
                    }
                }
                // gate epilogue
                int rowl = b0 + 16*mtA + (lane >> 2);
                #pragma unroll
                for (int nt = 0; nt < 4; nt++) {
                    int gc0 = 32*chA + 8*nt + 2*(lane & 3);
                    #pragma unroll
                    for (int rr = 0; rr < 2; rr++) {
                        int row = rowl + 8*rr;
                        const float* lx = Lxt + (size_t)row*NLX;
                        #pragma unroll
                        for (int jj = 0; jj < 2; jj++) {
                            int gc = gc0 + jj;
                            float a = acc[nt][2*rr + jj];
                            if (chA == 0) {
                                int j = j0 + gc;
                                g_zg[(size_t)row*KST + j] = fsigmoid(a + lx[j] + bg[j]);
                            } else {
                                int j = j0 + gc - 32;
                                size_t idx = (size_t)row*KST + j;
                                float r = fsigmoid(a + lx[KST + j] + bg[KST + j]);
                                split_store(g_us_hi, g_us_lo, idx, r * hin[idx]);
                            }
                        }
                    }
                }
            }
            grid_sync();

            // ================= phase B: lin GEMM + RK4 =================
            {
                float acc[2][4];
                acc[0][0]=0.f; acc[0][1]=0.f; acc[0][2]=0.f; acc[0][3]=0.f;
                acc[1][0]=0.f; acc[1][1]=0.f; acc[1][2]=0.f; acc[1][3]=0.f;
                const bf16* shp = g_us_hi + arow_off;
                const bf16* slp = g_us_lo + arow_off;
                #pragma unroll
                for (int c0 = 0; c0 < 2; c0++) {
                    uint32_t d = smu + RC_A + c0*RC_ABUF + sdst;
                    cp16(d,        shp + c0*32);
                    cp16(d + 5120, slp + c0*32);
                    CP_COMMIT();
                }
                #pragma unroll 1
                for (int c = 0; c < 16; c++) {
                    if (c < 15) { CP_WAIT(1); } else { CP_WAIT(0); }
                    __syncthreads();
                    if (c + 2 < 16) {
                        uint32_t d = smu + RC_A + ((c+2)%3)*RC_ABUF + sdst;
                        cp16(d,        shp + (c+2)*32);
                        cp16(d + 5120, slp + (c+2)*32);
                        CP_COMMIT();
                    }
                    uint32_t abase = smu + RC_A + (c%3)*RC_ABUF;
                    #pragma unroll
                    for (int ks = 0; ks < 2; ks++) {
                        uint32_t ah[4], al[4];
                        ldsm4(ah, abase + a_offA + ks*32);
                        ldsm4(al, abase + 5120 + a_offA + ks*32);
                        uint32_t kb = (uint32_t)(c*32 + ks*16 + b_k8)*2;
                        uint32_t bh[4], bl[4];
                        uint32_t bo = (uint32_t)(coB + b_row)*BSTR*2 + kb;
                        ldsm4(bh, smu + RC_WBHI + bo);
                        ldsm4(bl, smu + RC_WBLO + bo);
                        mma16816(acc[0], ah, bh[0], bh[1]);
                        mma16816(acc[1], ah, bh[2], bh[3]);
                        mma16816(acc[0], ah, bl[0], bl[1]);
                        mma16816(acc[1], ah, bl[2], bl[3]);
                        mma16816(acc[0], al, bh[0], bh[1]);
                        mma16816(acc[1], al, bh[2], bh[3]);
                    }
                }
                // RK4 epilogue
                int rowl = b0 + 16*mtA + (lane >> 2);
                #pragma unroll
                for (int rr = 0; rr < 2; rr++) {
                    int row = rowl + 8*rr;
                    float dt = (t > 0) ? seq[((size_t)(t-1)*B_SZ + row)*16 + 15] : 0.f;
                    const float* lx = Lxt + (size_t)row*NLX;
                    #pragma unroll
                    for (int nt = 0; nt < 2; nt++) {
                        int jl = coB + 8*nt + 2*(lane & 3);
                        #pragma unroll
                        for (int jj = 0; jj < 2; jj++) {
                            int j = j0 + jl + jj;
                            size_t idx = (size_t)row*KST + j;
                            float hv = hin[idx];
                            float kv = g_zg[idx] * (ftanh(acc[nt][2*rr + jj] + lx[2*KST + j] + blin[j]) - hv);
                            float ht;
                            if (s == 1)      { g_acc[idx]  = kv;      ht = g_h[idx] + dt*0.5f*kv; g_hA[idx] = ht; }
                            else if (s == 2) { g_acc[idx] += 2.f*kv;  ht = g_h[idx] + dt*0.5f*kv; g_hB[idx] = ht; }
                            else if (s == 3) { g_acc[idx] += 2.f*kv;  ht = g_h[idx] + dt*kv;      g_hA[idx] = ht; }
                            else {
                                ht = g_h[idx] + dt*(g_acc[idx] + kv)*(1.f/6.f);
                                g_h[idx] = ht;
                                split_store(g_st_hi, g_st_lo, (size_t)t*B_SZ*KST + idx, ht);
                            }
                            split_store(g_hs_hi, g_hs_lo, idx, ht);
                        }
                    }
                }
            }
            grid_sync();
        }
    }
}

// ---------------- out[1..255] = g_ty @ Ly2^T ----------------
__global__ void yout_kernel(const float* __restrict__ Ly2, float* __restrict__ out) {
    __shared__ float l2s[8*KST];
    int tid = threadIdx.x;
    for (int i = tid; i < 8*KST; i += 256) l2s[i] = Ly2[i];
    __syncthreads();
    int warp = tid >> 5, lane = tid & 31;
    int tok = blockIdx.x*8 + warp;
    const float* tr = g_ty + (size_t)tok*KST;
    float p[8] = {};
    for (int k = lane; k < KST; k += 32) {
        float tv = tr[k];
        #pragma unroll
        for (int o = 0; o < 8; o++) p[o] += tv*l2s[o*KST + k];
    }
    #pragma unroll
    for (int o = 0; o < 8; o++)
        #pragma unroll
        for (int off = 16; off; off >>= 1)
            p[o] += __shfl_xor_sync(0xffffffffu, p[o], off);
    if (lane == 0) {
        float* op = out + (size_t)(tok + B_SZ)*8;
        #pragma unroll
        for (int o = 0; o < 8; o++) op[o] = p[o];
    }
}

// ---------------- out[0] = Ly(h0) broadcast over batch ----------------
__global__ void y0_kernel(const float* __restrict__ state0,
                          const float* __restrict__ Ly1,
                          const float* __restrict__ Ly2,
                          float* __restrict__ out) {
    __shared__ float h0s[KST];
    __shared__ float tys[KST];
    __shared__ float y0s[8];
    int tid = threadIdx.x;
    for (int j = tid; j < KST; j += 256) h0s[j] = state0[j];
    __syncthreads();
    for (int j = tid; j < KST; j += 256) {
        float s = 0.f;
        const float* lr = Ly1 + (size_t)j*KST;
        for (int k = 0; k < KST; k++) s += h0s[k]*lr[k];
        tys[j] = tanhf(s);
    }
    __syncthreads();
    if (tid < 8) {
        float s = 0.f;
        const float* lr = Ly2 + (size_t)tid*KST;
        for (int k = 0; k < KST; k++) s += tys[k]*lr[k];
        y0s[tid] = s;
    }
    __syncthreads();
    for (int i = tid; i < B_SZ*8; i += 256) out[i] = y0s[i & 7];
}

// ---------------- launch ----------------
extern "C" void kernel_launch(void* const* d_in, const int* in_sizes, int n_in,
                              void* d_out, int out_size) {
    const float* seq    = (const float*)d_in[0];
    const float* state0 = (const float*)d_in[1];
    const float* Win    = (const float*)d_in[2];
    const float* bin    = (const float*)d_in[3];
    const float* Wx     = (const float*)d_in[4];
    const float* Wg     = (const float*)d_in[5];
    const float* bg     = (const float*)d_in[6];
    const float* Wlin   = (const float*)d_in[7];
    const float* blin   = (const float*)d_in[8];
    const float* Ly1    = (const float*)d_in[9];
    const float* Ly2    = (const float*)d_in[10];
    float* out = (float*)d_out;

    bf16 *xeh, *xel, *sth, *stl;
    float *Lx, *ty;
    cudaGetSymbolAddress((void**)&xeh, g_xe_hi);
    cudaGetSymbolAddress((void**)&xel, g_xe_lo);
    cudaGetSymbolAddress((void**)&sth, g_st_hi);
    cudaGetSymbolAddress((void**)&stl, g_st_lo);
    cudaGetSymbolAddress((void**)&Lx,  g_Lx);
    cudaGetSymbolAddress((void**)&ty,  g_ty);

    cudaFuncSetAttribute(recur_mma, cudaFuncAttributeMaxDynamicSharedMemorySize, RC_SMEM);
    cudaFuncSetAttribute(gemm_split<0>, cudaFuncAttributeMaxDynamicSharedMemorySize, GS_SMEM);
    cudaFuncSetAttribute(gemm_split<1>, cudaFuncAttributeMaxDynamicSharedMemorySize, GS_SMEM);

    embed_kernel<<<NTOK, 128>>>(seq, Win, bin);
    gemm_split<0><<<dim3(NTOK/128, NLX/64), 256, GS_SMEM>>>(xeh, xel, Wx, Lx, NLX);

    recur_mma<<<NBR, 256, RC_SMEM>>>(seq, state0, Wg, bg, Wlin, blin);

    gemm_split<1><<<dim3((NTOK - B_SZ)/128, KST/64), 256, GS_SMEM>>>(sth, stl, Ly1, ty, KST);
    yout_kernel<<<(NTOK - B_SZ)/8, 256>>>(Ly2, out);
    y0_kernel<<<1, 256>>>(state0, Ly1, Ly2, out);
}

// round 15
// speedup vs baseline: 1.3202x; 1.0716x over previous
#include <cuda_runtime.h>
#include <cuda_bf16.h>
#include <math.h>
#include <stdint.h>

#define L_SEQ 256
#define B_SZ  512
#define KIN   15
#define KST   512
#define NLX   1536
#define NTOK  (L_SEQ*B_SZ)   // 131072
#define NBR   128            // persistent CTAs for recurrence
#define BSTR  520            // weight-slab row stride (bf16 elems), 1040B rows
#define ASTR  40             // A-chunk row stride (bf16 elems)

typedef unsigned long long ull;
typedef __nv_bfloat16 bf16;

// ---------------- scratch (device globals; no allocation) ----------------
__device__ __align__(16) bf16 g_xe_hi[(size_t)NTOK*KST];
__device__ __align__(16) bf16 g_xe_lo[(size_t)NTOK*KST];
__device__ float g_Lx[(size_t)NTOK*NLX];
__device__ __align__(16) bf16 g_st_hi[(size_t)NTOK*KST];
__device__ __align__(16) bf16 g_st_lo[(size_t)NTOK*KST];
__device__ float g_ty[(size_t)(NTOK-B_SZ)*KST];
__device__ float g_h  [B_SZ*KST];
__device__ float g_hA [B_SZ*KST];
__device__ float g_hB [B_SZ*KST];
__device__ float g_acc[B_SZ*KST];
__device__ float g_zg [B_SZ*KST];
__device__ __align__(16) bf16 g_hs_hi[B_SZ*KST];
__device__ __align__(16) bf16 g_hs_lo[B_SZ*KST];
__device__ __align__(16) bf16 g_us_hi[B_SZ*KST];
__device__ __align__(16) bf16 g_us_lo[B_SZ*KST];
__device__ unsigned g_bar_count = 0;
__device__ volatile unsigned g_bar_gen = 0;

// ---------------- MUFU-free activations (FMA pipe only) ----------------
// fexp: e^x via 2^n * e^f split; deg-6 Taylor on |f*ln2| <= 0.347 (rel err ~1e-7).
__device__ __forceinline__ float fexp(float x) {
    float y = fminf(fmaxf(x*1.44269504f, -126.f), 126.f);
    float n = rintf(y);
    float t = (y - n)*0.69314718056f;
    float p = fmaf(t, 0.0013888889f, 0.0083333338f);
    p = fmaf(t, p, 0.041666668f);
    p = fmaf(t, p, 0.16666667f);
    p = fmaf(t, p, 0.5f);
    p = fmaf(t, p, 1.0f);
    p = fmaf(t, p, 1.0f);
    float sc = __int_as_float(((int)n + 127) << 23);
    return p*sc;
}
// frecip: valid for d >= 1 (our denominators are 1+e, e>=0); magic seed + 3 Newton.
__device__ __forceinline__ float frecip(float d) {
    float r = __int_as_float(0x7EF311C3 - __float_as_int(d));
    r = r*fmaf(-d, r, 2.f);
    r = r*fmaf(-d, r, 2.f);
    r = r*fmaf(-d, r, 2.f);
    return r;
}
__device__ __forceinline__ float fsigmoid(float x) { return frecip(1.f + fexp(-x)); }
__device__ __forceinline__ float ftanh(float x) {
    return 1.f - 2.f*frecip(fexp(2.f*x) + 1.f);
}

// ---------------- warp-MMA + async-copy primitives (sm_80+ baseline PTX) ----------------
__device__ __forceinline__ uint32_t smem_u32(const void* p) {
    uint32_t a;
    asm("{ .reg .u64 t; cvta.to.shared.u64 t, %1; cvt.u32.u64 %0, t; }" : "=r"(a) : "l"(p));
    return a;
}
__device__ __forceinline__ void ldsm4(uint32_t* r, uint32_t addr) {
    asm volatile("ldmatrix.sync.aligned.m8n8.x4.shared.b16 {%0,%1,%2,%3}, [%4];"
        : "=r"(r[0]), "=r"(r[1]), "=r"(r[2]), "=r"(r[3]) : "r"(addr));
}
__device__ __forceinline__ void mma16816(float* d, const uint32_t* a, uint32_t b0, uint32_t b1) {
    asm volatile("mma.sync.aligned.m16n8k16.row.col.f32.bf16.bf16.f32 "
        "{%0,%1,%2,%3}, {%4,%5,%6,%7}, {%8,%9}, {%0,%1,%2,%3};"
        : "+f"(d[0]), "+f"(d[1]), "+f"(d[2]), "+f"(d[3])
        : "r"(a[0]), "r"(a[1]), "r"(a[2]), "r"(a[3]), "r"(b0), "r"(b1));
}
__device__ __forceinline__ void cp16(uint32_t dst, const void* src) {
    asm volatile("cp.async.cg.shared.global [%0], [%1], 16;" :: "r"(dst), "l"(src));
}
#define CP_COMMIT() asm volatile("cp.async.commit_group;" ::: "memory")
#define CP_WAIT(n)  asm volatile("cp.async.wait_group %0;" :: "n"(n) : "memory")

__device__ __forceinline__ void split_store(bf16* hi, bf16* lo, size_t idx, float v) {
    bf16 h = __float2bfloat16(v);
    hi[idx] = h;
    lo[idx] = __float2bfloat16(v - __bfloat162float(h));
}

// software grid barrier across NBR CTAs (tight spin; all CTAs resident 1/SM)
__device__ __forceinline__ void grid_sync() {
    __syncthreads();
    if (threadIdx.x == 0) {
        __threadfence();
        unsigned g = g_bar_gen;
        if (atomicAdd(&g_bar_count, 1u) == (unsigned)(NBR - 1)) {
            g_bar_count = 0;
            __threadfence();
            g_bar_gen = g + 1u;
        } else {
            while (g_bar_gen == g) { }
            __threadfence();
        }
    }
    __syncthreads();
}

// ---------------- xe = tanh(x @ Win^T + bin), split to bf16 hi/lo ----------------
__global__ void embed_kernel(const float* __restrict__ seq,
                             const float* __restrict__ Win,
                             const float* __restrict__ bin) {
    int tok = blockIdx.x;
    __shared__ float xs[KIN];
    if (threadIdx.x < KIN) xs[threadIdx.x] = seq[(size_t)tok*16 + threadIdx.x];
    __syncthreads();
    for (int j = threadIdx.x; j < KST; j += blockDim.x) {
        float s = bin[j];
        const float* wr = Win + j*KIN;
        #pragma unroll
        for (int i = 0; i < KIN; i++) s += xs[i]*wr[i];
        split_store(g_xe_hi, g_xe_lo, (size_t)tok*KST + j, ftanh(s));
    }
}

// ---------------- split-bf16 GEMM: C = act(A @ B^T), tile 128x64, K=512 ----------------
// cp.async depth-2 pipelined A chunks (k=32, 3 bufs); B slab staged once. 256 thr.
#define GS_WHI  0
#define GS_WLO  66560
#define GS_A    133120
#define GS_ABUF 20480
#define GS_SMEM (GS_A + 3*GS_ABUF)   // 194560
template<int TANH>
__global__ void __launch_bounds__(256) gemm_split(
    const bf16* __restrict__ Ahi, const bf16* __restrict__ Alo,
    const float* __restrict__ B, float* __restrict__ C, int N)
{
    extern __shared__ char sm[];
    uint32_t smu = smem_u32(sm);
    int tid = threadIdx.x;
    int w = tid >> 5, lane = tid & 31;
    int bm = blockIdx.x*128, bn = blockIdx.y*64;

    for (int e = tid; e < 64*KST; e += 256) {
        int n = e >> 9, k = e & (KST-1);
        float v = B[(size_t)(bn + n)*KST + k];
        bf16 h = __float2bfloat16(v);
        size_t o = (size_t)n*BSTR + k;
        ((bf16*)(sm + GS_WHI))[o] = h;
        ((bf16*)(sm + GS_WLO))[o] = __float2bfloat16(v - __bfloat162float(h));
    }

    float acc[8][4];
    #pragma unroll
    for (int i = 0; i < 8; i++) { acc[i][0]=0.f; acc[i][1]=0.f; acc[i][2]=0.f; acc[i][3]=0.f; }

    uint32_t a_off = ((uint32_t)(16*w + (lane & 15))*ASTR + ((lane >> 4) << 3)) * 2;
    uint32_t b_row = (lane & 7) + ((lane & 16) >> 1);
    uint32_t b_k8  = (lane & 8);

    int srow = tid >> 1, skc = (tid & 1)*16;
    const bf16* ahp = Ahi + (size_t)(bm + srow)*KST + skc;
    const bf16* alp = Alo + (size_t)(bm + srow)*KST + skc;
    uint32_t sdst = (uint32_t)(srow*ASTR + skc)*2;

    #pragma unroll
    for (int c0 = 0; c0 < 2; c0++) {
        uint32_t d = smu + GS_A + c0*GS_ABUF + sdst;
        const bf16* ah = ahp + c0*32;
        const bf16* al = alp + c0*32;
        cp16(d, ah);          cp16(d + 16, ah + 8);
        cp16(d + 10240, al);  cp16(d + 10240 + 16, al + 8);
        CP_COMMIT();
    }
    __syncthreads();

    #pragma unroll 1
    for (int c = 0; c < 16; c++) {
        if (c < 15) { CP_WAIT(1); } else { CP_WAIT(0); }
        __syncthreads();
        if (c + 2 < 16) {
            uint32_t d = smu + GS_A + ((c+2)%3)*GS_ABUF + sdst;
            const bf16* ah = ahp + (c+2)*32;
            const bf16* al = alp + (c+2)*32;
            cp16(d, ah);          cp16(d + 16, ah + 8);
            cp16(d + 10240, al);  cp16(d + 10240 + 16, al + 8);
            CP_COMMIT();
        }
        uint32_t abase = smu + GS_A + (c%3)*GS_ABUF;
        #pragma unroll
        for (int ks = 0; ks < 2; ks++) {
            uint32_t ah[4], al[4];
            ldsm4(ah, abase + a_off + ks*32);
            ldsm4(al, abase + 10240 + a_off + ks*32);
            uint32_t kb = (uint32_t)(c*32 + ks*16 + b_k8)*2;
            #pragma unroll
            for (int p = 0; p < 4; p++) {
                uint32_t bh[4], bl[4];
                uint32_t bo = (uint32_t)(16*p + b_row)*BSTR*2 + kb;
                ldsm4(bh, smu + GS_WHI + bo);
                ldsm4(bl, smu + GS_WLO + bo);
                mma16816(acc[2*p],   ah, bh[0], bh[1]);
                mma16816(acc[2*p+1], ah, bh[2], bh[3]);
                mma16816(acc[2*p],   ah, bl[0], bl[1]);
                mma16816(acc[2*p+1], ah, bl[2], bl[3]);
                mma16816(acc[2*p],   al, bh[0], bh[1]);
                mma16816(acc[2*p+1], al, bh[2], bh[3]);
            }
        }
    }

    int rowl = bm + 16*w + (lane >> 2);
    #pragma unroll
    for (int nt = 0; nt < 8; nt++) {
        int col = bn + 8*nt + 2*(lane & 3);
        #pragma unroll
        for (int rr = 0; rr < 2; rr++) {
            size_t ro = (size_t)(rowl + 8*rr)*N + col;
            float v0 = acc[nt][2*rr], v1 = acc[nt][2*rr+1];
            if (TANH) { v0 = ftanh(v0); v1 = ftanh(v1); }
            C[ro] = v0; C[ro + 1] = v1;
        }
    }
}

// ---------------- persistent recurrence kernel (R14 structure, MUFU-free epilogues) ----------------
#define RC_WAHI 0
#define RC_WALO 66560
#define RC_WBHI 133120
#define RC_WBLO 166400
#define RC_A    199680          // 3 bufs x (hi 5120 + lo 5120)
#define RC_ABUF 10240
#define RC_SMEM (RC_A + 3*RC_ABUF)   // 230400
__global__ void __launch_bounds__(256, 1) recur_mma(
    const float* __restrict__ seq, const float* __restrict__ state0,
    const float* __restrict__ Wg, const float* __restrict__ bg,
    const float* __restrict__ Wlin, const float* __restrict__ blin)
{
    extern __shared__ char sm[];
    uint32_t smu = smem_u32(sm);
    int tid = threadIdx.x;
    int w = tid >> 5, lane = tid & 31;
    int cta = blockIdx.x;
    int b0 = (cta & 7)*64;
    int j0 = (cta >> 3)*32;

    for (int e = tid; e < 64*KST; e += 256) {
        int n = e >> 9, k = e & (KST-1);
        int grow = (n < 32) ? (j0 + n) : (KST + j0 + n - 32);
        float v = Wg[(size_t)grow*KST + k];
        bf16 h = __float2bfloat16(v);
        size_t o = (size_t)n*BSTR + k;
        ((bf16*)(sm + RC_WAHI))[o] = h;
        ((bf16*)(sm + RC_WALO))[o] = __float2bfloat16(v - __bfloat162float(h));
    }
    for (int e = tid; e < 32*KST; e += 256) {
        int n = e >> 9, k = e & (KST-1);
        float v = Wlin[(size_t)(j0 + n)*KST + k];
        bf16 h = __float2bfloat16(v);
        size_t o = (size_t)n*BSTR + k;
        ((bf16*)(sm + RC_WBHI))[o] = h;
        ((bf16*)(sm + RC_WBLO))[o] = __float2bfloat16(v - __bfloat162float(h));
    }
    for (int idx = cta*256 + tid; idx < B_SZ*KST; idx += NBR*256) {
        float h0 = state0[idx & (KST-1)];
        g_h[idx] = h0;
        split_store(g_hs_hi, g_hs_lo, idx, h0);
    }
    grid_sync();

    int mtA = w & 3, chA = w >> 2;
    int coB = (w >> 2)*16;
    uint32_t a_offA = ((uint32_t)(16*mtA + (lane & 15))*ASTR + ((lane >> 4) << 3)) * 2;
    uint32_t b_row = (lane & 7) + ((lane & 16) >> 1);
    uint32_t b_k8  = (lane & 8);

    int srow = tid >> 2, skc = (tid & 3)*8;
    uint32_t sdst = (uint32_t)(srow*ASTR + skc)*2;
    const size_t arow_off = (size_t)(b0 + srow)*KST + skc;

    #pragma unroll 1
    for (int t = 0; t < L_SEQ; ++t) {
        const float* Lxt = g_Lx + (size_t)t*B_SZ*NLX;
        #pragma unroll 1
        for (int s = 1; s <= 4; ++s) {
            const float* hin = (s==1) ? g_h : (s==2 ? g_hA : (s==3 ? g_hB : g_hA));

            // ================= phase A: gate GEMM (z,r) =================
            {
                float acc[4][4];
                #pragma unroll
                for (int i = 0; i < 4; i++) { acc[i][0]=0.f; acc[i][1]=0.f; acc[i][2]=0.f; acc[i][3]=0.f; }
                const bf16* shp = g_hs_hi + arow_off;
                const bf16* slp = g_hs_lo + arow_off;
                #pragma unroll
                for (int c0 = 0; c0 < 2; c0++) {
                    uint32_t d = smu + RC_A + c0*RC_ABUF + sdst;
                    cp16(d,        shp + c0*32);
                    cp16(d + 5120, slp + c0*32);
                    CP_COMMIT();
                }
                #pragma unroll 1
                for (int c = 0; c < 16; c++) {
                    if (c < 15) { CP_WAIT(1); } else { CP_WAIT(0); }
                    __syncthreads();
                    if (c + 2 < 16) {
                        uint32_t d = smu + RC_A + ((c+2)%3)*RC_ABUF + sdst;
                        cp16(d,        shp + (c+2)*32);
                        cp16(d + 5120, slp + (c+2)*32);
                        CP_COMMIT();
                    }
                    uint32_t abase = smu + RC_A + (c%3)*RC_ABUF;
                    #pragma unroll
                    for (int ks = 0; ks < 2; ks++) {
                        uint32_t ah[4], al[4];
                        ldsm4(ah, abase + a_offA + ks*32);
                        ldsm4(al, abase + 5120 + a_offA + ks*32);
                        uint32_t kb = (uint32_t)(c*32 + ks*16 + b_k8)*2;
                        #pragma unroll
                        for (int p = 0; p < 2; p++) {
                            uint32_t bh[4], bl[4];
                            uint32_t bo = (uint32_t)(32*chA + 16*p + b_row)*BSTR*2 + kb;
                            ldsm4(bh, smu + RC_WAHI + bo);
                            ldsm4(bl, smu + RC_WALO + bo);
                            mma16816(acc[2*p],   ah, bh[0], bh[1]);
                            mma16816(acc[2*p+1], ah, bh[2], bh[3]);
                            mma16816(acc[2*p],   ah, bl[0], bl[1]);
                            mma16816(acc[2*p+1], ah, bl[2], bl[3]);
                            mma16816(acc[2*p],   al, bh[0], bh[1]);
                            mma16816(acc[2*p+1], al, bh[2], bh[3]);
                        }
                    }
                }
                int rowl = b0 + 16*mtA + (lane >> 2);
                #pragma unroll
                for (int nt = 0; nt < 4; nt++) {
                    int gc0 = 32*chA + 8*nt + 2*(lane & 3);
                    #pragma unroll
                    for (int rr = 0; rr < 2; rr++) {
                        int row = rowl + 8*rr;
                        const float* lx = Lxt + (size_t)row*NLX;
                        #pragma unroll
                        for (int jj = 0; jj < 2; jj++) {
                            int gc = gc0 + jj;
                            float a = acc[nt][2*rr + jj];
                            if (chA == 0) {
                                int j = j0 + gc;
                                g_zg[(size_t)row*KST + j] = fsigmoid(a + lx[j] + bg[j]);
                            } else {
                                int j = j0 + gc - 32;
                                size_t idx = (size_t)row*KST + j;
                                float r = fsigmoid(a + lx[KST + j] + bg[KST + j]);
                                split_store(g_us_hi, g_us_lo, idx, r * hin[idx]);
                            }
                        }
                    }
                }
            }
            grid_sync();

            // ================= phase B: lin GEMM + RK4 =================
            {
                float acc[2][4];
                acc[0][0]=0.f; acc[0][1]=0.f; acc[0][2]=0.f; acc[0][3]=0.f;
                acc[1][0]=0.f; acc[1][1]=0.f; acc[1][2]=0.f; acc[1][3]=0.f;
                const bf16* shp = g_us_hi + arow_off;
                const bf16* slp = g_us_lo + arow_off;
                #pragma unroll
                for (int c0 = 0; c0 < 2; c0++) {
                    uint32_t d = smu + RC_A + c0*RC_ABUF + sdst;
                    cp16(d,        shp + c0*32);
                    cp16(d + 5120, slp + c0*32);
                    CP_COMMIT();
                }
                #pragma unroll 1
                for (int c = 0; c < 16; c++) {
                    if (c < 15) { CP_WAIT(1); } else { CP_WAIT(0); }
                    __syncthreads();
                    if (c + 2 < 16) {
                        uint32_t d = smu + RC_A + ((c+2)%3)*RC_ABUF + sdst;
                        cp16(d,        shp + (c+2)*32);
                        cp16(d + 5120, slp + (c+2)*32);
                        CP_COMMIT();
                    }
                    uint32_t abase = smu + RC_A + (c%3)*RC_ABUF;
                    #pragma unroll
                    for (int ks = 0; ks < 2; ks++) {
                        uint32_t ah[4], al[4];
                        ldsm4(ah, abase + a_offA + ks*32);
                        ldsm4(al, abase + 5120 + a_offA + ks*32);
                        uint32_t kb = (uint32_t)(c*32 + ks*16 + b_k8)*2;
                        uint32_t bh[4], bl[4];
                        uint32_t bo = (uint32_t)(coB + b_row)*BSTR*2 + kb;
                        ldsm4(bh, smu + RC_WBHI + bo);
                        ldsm4(bl, smu + RC_WBLO + bo);
                        mma16816(acc[0], ah, bh[0], bh[1]);
                        mma16816(acc[1], ah, bh[2], bh[3]);
                        mma16816(acc[0], ah, bl[0], bl[1]);
                        mma16816(acc[1], ah, bl[2], bl[3]);
                        mma16816(acc[0], al, bh[0], bh[1]);
                        mma16816(acc[1], al, bh[2], bh[3]);
                    }
                }
                int rowl = b0 + 16*mtA + (lane >> 2);
                #pragma unroll
                for (int rr = 0; rr < 2; rr++) {
                    int row = rowl + 8*rr;
                    float dt = (t > 0) ? seq[((size_t)(t-1)*B_SZ + row)*16 + 15] : 0.f;
                    const float* lx = Lxt + (size_t)row*NLX;
                    #pragma unroll
                    for (int nt = 0; nt < 2; nt++) {
                        int jl = coB + 8*nt + 2*(lane & 3);
                        #pragma unroll
                        for (int jj = 0; jj < 2; jj++) {
                            int j = j0 + jl + jj;
                            size_t idx = (size_t)row*KST + j;
                            float hv = hin[idx];
                            float kv = g_zg[idx] * (ftanh(acc[nt][2*rr + jj] + lx[2*KST + j] + blin[j]) - hv);
                            float ht;
                            if (s == 1)      { g_acc[idx]  = kv;      ht = g_h[idx] + dt*0.5f*kv; g_hA[idx] = ht; }
                            else if (s == 2) { g_acc[idx] += 2.f*kv;  ht = g_h[idx] + dt*0.5f*kv; g_hB[idx] = ht; }
                            else if (s == 3) { g_acc[idx] += 2.f*kv;  ht = g_h[idx] + dt*kv;      g_hA[idx] = ht; }
                            else {
                                ht = g_h[idx] + dt*(g_acc[idx] + kv)*(1.f/6.f);
                                g_h[idx] = ht;
                                split_store(g_st_hi, g_st_lo, (size_t)t*B_SZ*KST + idx, ht);
                            }
                            split_store(g_hs_hi, g_hs_lo, idx, ht);
                        }
                    }
                }
            }
            grid_sync();
        }
    }
}

// ---------------- out[1..255] = g_ty @ Ly2^T ----------------
__global__ void yout_kernel(const float* __restrict__ Ly2, float* __restrict__ out) {
    __shared__ float l2s[8*KST];
    int tid = threadIdx.x;
    for (int i = tid; i < 8*KST; i += 256) l2s[i] = Ly2[i];
    __syncthreads();
    int warp = tid >> 5, lane = tid & 31;
    int tok = blockIdx.x*8 + warp;
    const float* tr = g_ty + (size_t)tok*KST;
    float p[8] = {};
    for (int k = lane; k < KST; k += 32) {
        float tv = tr[k];
        #pragma unroll
        for (int o = 0; o < 8; o++) p[o] += tv*l2s[o*KST + k];
    }
    #pragma unroll
    for (int o = 0; o < 8; o++)
        #pragma unroll
        for (int off = 16; off; off >>= 1)
            p[o] += __shfl_xor_sync(0xffffffffu, p[o], off);
    if (lane == 0) {
        float* op = out + (size_t)(tok + B_SZ)*8;
        #pragma unroll
        for (int o = 0; o < 8; o++) op[o] = p[o];
    }
}

// ---------------- out[0] = Ly(h0) broadcast over batch ----------------
__global__ void y0_kernel(const float* __restrict__ state0,
                          const float* __restrict__ Ly1,
                          const float* __restrict__ Ly2,
                          float* __restrict__ out) {
    __shared__ float h0s[KST];
    __shared__ float tys[KST];
    __shared__ float y0s[8];
    int tid = threadIdx.x;
    for (int j = tid; j < KST; j += 256) h0s[j] = state0[j];
    __syncthreads();
    for (int j = tid; j < KST; j += 256) {
        float s = 0.f;
        const float* lr = Ly1 + (size_t)j*KST;
        for (int k = 0; k < KST; k++) s += h0s[k]*lr[k];
        tys[j] = tanhf(s);
    }
    __syncthreads();
    if (tid < 8) {
        float s = 0.f;
        const float* lr = Ly2 + (size_t)tid*KST;
        for (int k = 0; k < KST; k++) s += tys[k]*lr[k];
        y0s[tid] = s;
    }
    __syncthreads();
    for (int i = tid; i < B_SZ*8; i += 256) out[i] = y0s[i & 7];
}

// ---------------- launch ----------------
extern "C" void kernel_launch(void* const* d_in, const int* in_sizes, int n_in,
                              void* d_out, int out_size) {
    const float* seq    = (const float*)d_in[0];
    const float* state0 = (const float*)d_in[1];
    const float* Win    = (const float*)d_in[2];
    const float* bin    = (const float*)d_in[3];
    const float* Wx     = (const float*)d_in[4];
    const float* Wg     = (const float*)d_in[5];
    const float* bg     = (const float*)d_in[6];
    const float* Wlin   = (const float*)d_in[7];
    const float* blin   = (const float*)d_in[8];
    const float* Ly1    = (const float*)d_in[9];
    const float* Ly2    = (const float*)d_in[10];
    float* out = (float*)d_out;

    bf16 *xeh, *xel, *sth, *stl;
    float *Lx, *ty;
    cudaGetSymbolAddress((void**)&xeh, g_xe_hi);
    cudaGetSymbolAddress((void**)&xel, g_xe_lo);
    cudaGetSymbolAddress((void**)&sth, g_st_hi);
    cudaGetSymbolAddress((void**)&stl, g_st_lo);
    cudaGetSymbolAddress((void**)&Lx,  g_Lx);
    cudaGetSymbolAddress((void**)&ty,  g_ty);

    cudaFuncSetAttribute(recur_mma, cudaFuncAttributeMaxDynamicSharedMemorySize, RC_SMEM);
    cudaFuncSetAttribute(gemm_split<0>, cudaFuncAttributeMaxDynamicSharedMemorySize, GS_SMEM);
    cudaFuncSetAttribute(gemm_split<1>, cudaFuncAttributeMaxDynamicSharedMemorySize, GS_SMEM);

    embed_kernel<<<NTOK, 128>>>(seq, Win, bin);
    gemm_split<0><<<dim3(NTOK/128, NLX/64), 256, GS_SMEM>>>(xeh, xel, Wx, Lx, NLX);

    recur_mma<<<NBR, 256, RC_SMEM>>>(seq, state0, Wg, bg, Wlin, blin);

    gemm_split<1><<<dim3((NTOK - B_SZ)/128, KST/64), 256, GS_SMEM>>>(sth, stl, Ly1, ty, KST);
    yout_kernel<<<(NTOK - B_SZ)/8, 256>>>(Ly2, out);
    y0_kernel<<<1, 256>>>(state0, Ly1, Ly2, out);
}

// round 16
// speedup vs baseline: 1.5475x; 1.1722x over previous
#include <cuda_runtime.h>
#include <cuda_bf16.h>
#include <cuda_fp16.h>
#include <math.h>
#include <stdint.h>

#define L_SEQ 256
#define B_SZ  512
#define KIN   15
#define KST   512
#define NLX   1536
#define NTOK  (L_SEQ*B_SZ)   // 131072
#define NBR   128            // persistent CTAs for recurrence
#define BSTR  520            // weight-slab row stride (fp16 elems), 1040B rows
#define ASTR  40             // A-chunk row stride (fp16 elems)

typedef unsigned long long ull;
typedef __half h16;

// ---------------- scratch (device globals; no allocation) ----------------
__device__ __align__(16) h16 g_xe_hi[(size_t)NTOK*KST];
__device__ __align__(16) h16 g_xe_lo[(size_t)NTOK*KST];
__device__ float g_Lx[(size_t)NTOK*NLX];
__device__ __align__(16) h16 g_st_hi[(size_t)NTOK*KST];
__device__ __align__(16) h16 g_st_lo[(size_t)NTOK*KST];
__device__ float g_ty[(size_t)(NTOK-B_SZ)*KST];
__device__ float g_h  [B_SZ*KST];
__device__ float g_hA [B_SZ*KST];
__device__ float g_hB [B_SZ*KST];
__device__ float g_acc[B_SZ*KST];
__device__ float g_zg [B_SZ*KST];
__device__ __align__(16) h16 g_hs_hi[B_SZ*KST];
__device__ __align__(16) h16 g_hs_lo[B_SZ*KST];
__device__ __align__(16) h16 g_us_hi[B_SZ*KST];
__device__ __align__(16) h16 g_us_lo[B_SZ*KST];
__device__ unsigned g_bar_count = 0;
__device__ volatile unsigned g_bar_gen = 0;

// ---------------- MUFU-free activations (FMA pipe only) ----------------
__device__ __forceinline__ float fexp(float x) {
    float y = fminf(fmaxf(x*1.44269504f, -126.f), 126.f);
    float n = rintf(y);
    float t = (y - n)*0.69314718056f;
    float p = fmaf(t, 0.0013888889f, 0.0083333338f);
    p = fmaf(t, p, 0.041666668f);
    p = fmaf(t, p, 0.16666667f);
    p = fmaf(t, p, 0.5f);
    p = fmaf(t, p, 1.0f);
    p = fmaf(t, p, 1.0f);
    float sc = __int_as_float(((int)n + 127) << 23);
    return p*sc;
}
__device__ __forceinline__ float frecip(float d) {
    float r = __int_as_float(0x7EF311C3 - __float_as_int(d));
    r = r*fmaf(-d, r, 2.f);
    r = r*fmaf(-d, r, 2.f);
    r = r*fmaf(-d, r, 2.f);
    return r;
}
__device__ __forceinline__ float fsigmoid(float x) { return frecip(1.f + fexp(-x)); }
__device__ __forceinline__ float ftanh(float x) {
    return 1.f - 2.f*frecip(fexp(2.f*x) + 1.f);
}

// ---------------- warp-MMA + async-copy primitives (sm_80+ baseline PTX) ----------------
__device__ __forceinline__ uint32_t smem_u32(const void* p) {
    uint32_t a;
    asm("{ .reg .u64 t; cvta.to.shared.u64 t, %1; cvt.u32.u64 %0, t; }" : "=r"(a) : "l"(p));
    return a;
}
__device__ __forceinline__ void ldsm4(uint32_t* r, uint32_t addr) {
    asm volatile("ldmatrix.sync.aligned.m8n8.x4.shared.b16 {%0,%1,%2,%3}, [%4];"
        : "=r"(r[0]), "=r"(r[1]), "=r"(r[2]), "=r"(r[3]) : "r"(addr));
}
// fp16 MMA, fp32 accum
__device__ __forceinline__ void mma16816(float* d, const uint32_t* a, uint32_t b0, uint32_t b1) {
    asm volatile("mma.sync.aligned.m16n8k16.row.col.f32.f16.f16.f32 "
        "{%0,%1,%2,%3}, {%4,%5,%6,%7}, {%8,%9}, {%0,%1,%2,%3};"
        : "+f"(d[0]), "+f"(d[1]), "+f"(d[2]), "+f"(d[3])
        : "r"(a[0]), "r"(a[1]), "r"(a[2]), "r"(a[3]), "r"(b0), "r"(b1));
}
__device__ __forceinline__ void cp16(uint32_t dst, const void* src) {
    asm volatile("cp.async.cg.shared.global [%0], [%1], 16;" :: "r"(dst), "l"(src));
}
#define CP_COMMIT() asm volatile("cp.async.commit_group;" ::: "memory")
#define CP_WAIT(n)  asm volatile("cp.async.wait_group %0;" :: "n"(n) : "memory")

// fp16 hi/lo split store (hi+lo carries ~22 mantissa bits of v)
__device__ __forceinline__ void split_store(h16* hi, h16* lo, size_t idx, float v) {
    h16 h = __float2half_rn(v);
    hi[idx] = h;
    lo[idx] = __float2half_rn(v - __half2float(h));
}

// software grid barrier across NBR CTAs (tight spin; all CTAs resident 1/SM)
__device__ __forceinline__ void grid_sync() {
    __syncthreads();
    if (threadIdx.x == 0) {
        __threadfence();
        unsigned g = g_bar_gen;
        if (atomicAdd(&g_bar_count, 1u) == (unsigned)(NBR - 1)) {
            g_bar_count = 0;
            __threadfence();
            g_bar_gen = g + 1u;
        } else {
            while (g_bar_gen == g) { }
            __threadfence();
        }
    }
    __syncthreads();
}

// ---------------- xe = tanh(x @ Win^T + bin), split to fp16 hi/lo ----------------
__global__ void embed_kernel(const float* __restrict__ seq,
                             const float* __restrict__ Win,
                             const float* __restrict__ bin) {
    int tok = blockIdx.x;
    __shared__ float xs[KIN];
    if (threadIdx.x < KIN) xs[threadIdx.x] = seq[(size_t)tok*16 + threadIdx.x];
    __syncthreads();
    for (int j = threadIdx.x; j < KST; j += blockDim.x) {
        float s = bin[j];
        const float* wr = Win + j*KIN;
        #pragma unroll
        for (int i = 0; i < KIN; i++) s += xs[i]*wr[i];
        split_store(g_xe_hi, g_xe_lo, (size_t)tok*KST + j, ftanh(s));
    }
}

// ---------------- 2-pass split-fp16 GEMM: C = act(A @ B^T), tile 128x64, K=512 ----------------
// B rounded to single fp16 in smem; A as hi/lo. cp.async depth-2 pipeline. 256 thr.
#define GS_W    0               // 64 x 520 fp16 = 66560
#define GS_A    66560
#define GS_ABUF 20480           // hi 10240 + lo 10240
#define GS_SMEM (GS_A + 3*GS_ABUF)   // 128000
template<int TANH>
__global__ void __launch_bounds__(256) gemm_split(
    const h16* __restrict__ Ahi, const h16* __restrict__ Alo,
    const float* __restrict__ B, float* __restrict__ C, int N)
{
    extern __shared__ char sm[];
    uint32_t smu = smem_u32(sm);
    int tid = threadIdx.x;
    int w = tid >> 5, lane = tid & 31;
    int bm = blockIdx.x*128, bn = blockIdx.y*64;

    for (int e = tid; e < 64*KST; e += 256) {
        int n = e >> 9, k = e & (KST-1);
        float v = B[(size_t)(bn + n)*KST + k];
        ((h16*)(sm + GS_W))[(size_t)n*BSTR + k] = __float2half_rn(v);
    }

    float acc[8][4];
    #pragma unroll
    for (int i = 0; i < 8; i++) { acc[i][0]=0.f; acc[i][1]=0.f; acc[i][2]=0.f; acc[i][3]=0.f; }

    uint32_t a_off = ((uint32_t)(16*w + (lane & 15))*ASTR + ((lane >> 4) << 3)) * 2;
    uint32_t b_row = (lane & 7) + ((lane & 16) >> 1);
    uint32_t b_k8  = (lane & 8);

    int srow = tid >> 1, skc = (tid & 1)*16;
    const h16* ahp = Ahi + (size_t)(bm + srow)*KST + skc;
    const h16* alp = Alo + (size_t)(bm + srow)*KST + skc;
    uint32_t sdst = (uint32_t)(srow*ASTR + skc)*2;

    #pragma unroll
    for (int c0 = 0; c0 < 2; c0++) {
        uint32_t d = smu + GS_A + c0*GS_ABUF + sdst;
        const h16* ah = ahp + c0*32;
        const h16* al = alp + c0*32;
        cp16(d, ah);          cp16(d + 16, ah + 8);
        cp16(d + 10240, al);  cp16(d + 10240 + 16, al + 8);
        CP_COMMIT();
    }
    __syncthreads();

    #pragma unroll 1
    for (int c = 0; c < 16; c++) {
        if (c < 15) { CP_WAIT(1); } else { CP_WAIT(0); }
        __syncthreads();
        if (c + 2 < 16) {
            uint32_t d = smu + GS_A + ((c+2)%3)*GS_ABUF + sdst;
            const h16* ah = ahp + (c+2)*32;
            const h16* al = alp + (c+2)*32;
            cp16(d, ah);          cp16(d + 16, ah + 8);
            cp16(d + 10240, al);  cp16(d + 10240 + 16, al + 8);
            CP_COMMIT();
        }
        uint32_t abase = smu + GS_A + (c%3)*GS_ABUF;
        #pragma unroll
        for (int ks = 0; ks < 2; ks++) {
            uint32_t ah[4], al[4];
            ldsm4(ah, abase + a_off + ks*32);
            ldsm4(al, abase + 10240 + a_off + ks*32);
            uint32_t kb = (uint32_t)(c*32 + ks*16 + b_k8)*2;
            #pragma unroll
            for (int p = 0; p < 4; p++) {
                uint32_t bh[4];
                ldsm4(bh, smu + GS_W + (uint32_t)(16*p + b_row)*BSTR*2 + kb);
                mma16816(acc[2*p],   ah, bh[0], bh[1]);
                mma16816(acc[2*p+1], ah, bh[2], bh[3]);
                mma16816(acc[2*p],   al, bh[0], bh[1]);
                mma16816(acc[2*p+1], al, bh[2], bh[3]);
            }
        }
    }

    int rowl = bm + 16*w + (lane >> 2);
    #pragma unroll
    for (int nt = 0; nt < 8; nt++) {
        int col = bn + 8*nt + 2*(lane & 3);
        #pragma unroll
        for (int rr = 0; rr < 2; rr++) {
            size_t ro = (size_t)(rowl + 8*rr)*N + col;
            float v0 = acc[nt][2*rr], v1 = acc[nt][2*rr+1];
            if (TANH) { v0 = ftanh(v0); v1 = ftanh(v1); }
            C[ro] = v0; C[ro + 1] = v1;
        }
    }
}

// ---------------- persistent recurrence kernel (2-pass split-fp16) ----------------
// 128 CTAs x 256 thr. CTA: b0 = (cta&7)*64 rows, j0 = (cta>>3)*32 state cols.
// Weights single fp16 in smem (gates 64 rows + lin 32 rows); A (h/u) split hi/lo.
#define RC_WA   0               // gates: 64 x 520 fp16 = 66560
#define RC_WB   66560           // lin:   32 x 520 fp16 = 33280
#define RC_A    99840           // 3 bufs x (hi 5120 + lo 5120)
#define RC_ABUF 10240
#define RC_SMEM (RC_A + 3*RC_ABUF)   // 130560
__global__ void __launch_bounds__(256, 1) recur_mma(
    const float* __restrict__ seq, const float* __restrict__ state0,
    const float* __restrict__ Wg, const float* __restrict__ bg,
    const float* __restrict__ Wlin, const float* __restrict__ blin)
{
    extern __shared__ char sm[];
    uint32_t smu = smem_u32(sm);
    int tid = threadIdx.x;
    int w = tid >> 5, lane = tid & 31;
    int cta = blockIdx.x;
    int b0 = (cta & 7)*64;
    int j0 = (cta >> 3)*32;

    for (int e = tid; e < 64*KST; e += 256) {
        int n = e >> 9, k = e & (KST-1);
        int grow = (n < 32) ? (j0 + n) : (KST + j0 + n - 32);
        ((h16*)(sm + RC_WA))[(size_t)n*BSTR + k] = __float2half_rn(Wg[(size_t)grow*KST + k]);
    }
    for (int e = tid; e < 32*KST; e += 256) {
        int n = e >> 9, k = e & (KST-1);
        ((h16*)(sm + RC_WB))[(size_t)n*BSTR + k] = __float2half_rn(Wlin[(size_t)(j0 + n)*KST + k]);
    }
    for (int idx = cta*256 + tid; idx < B_SZ*KST; idx += NBR*256) {
        float h0 = state0[idx & (KST-1)];
        g_h[idx] = h0;
        split_store(g_hs_hi, g_hs_lo, idx, h0);
    }
    grid_sync();

    int mtA = w & 3, chA = w >> 2;
    int coB = (w >> 2)*16;
    uint32_t a_offA = ((uint32_t)(16*mtA + (lane & 15))*ASTR + ((lane >> 4) << 3)) * 2;
    uint32_t b_row = (lane & 7) + ((lane & 16) >> 1);
    uint32_t b_k8  = (lane & 8);

    int srow = tid >> 2, skc = (tid & 3)*8;
    uint32_t sdst = (uint32_t)(srow*ASTR + skc)*2;
    const size_t arow_off = (size_t)(b0 + srow)*KST + skc;

    #pragma unroll 1
    for (int t = 0; t < L_SEQ; ++t) {
        const float* Lxt = g_Lx + (size_t)t*B_SZ*NLX;
        #pragma unroll 1
        for (int s = 1; s <= 4; ++s) {
            const float* hin = (s==1) ? g_h : (s==2 ? g_hA : (s==3 ? g_hB : g_hA));

            // ================= phase A: gate GEMM (z,r) =================
            {
                float acc[4][4];
                #pragma unroll
                for (int i = 0; i < 4; i++) { acc[i][0]=0.f; acc[i][1]=0.f; acc[i][2]=0.f; acc[i][3]=0.f; }
                const h16* shp = g_hs_hi + arow_off;
                const h16* slp = g_hs_lo + arow_off;
                #pragma unroll
                for (int c0 = 0; c0 < 2; c0++) {
                    uint32_t d = smu + RC_A + c0*RC_ABUF + sdst;
                    cp16(d,        shp + c0*32);
                    cp16(d + 5120, slp + c0*32);
                    CP_COMMIT();
                }
                #pragma unroll 1
                for (int c = 0; c < 16; c++) {
                    if (c < 15) { CP_WAIT(1); } else { CP_WAIT(0); }
                    __syncthreads();
                    if (c + 2 < 16) {
                        uint32_t d = smu + RC_A + ((c+2)%3)*RC_ABUF + sdst;
                        cp16(d,        shp + (c+2)*32);
                        cp16(d + 5120, slp + (c+2)*32);
                        CP_COMMIT();
                    }
                    uint32_t abase = smu + RC_A + (c%3)*RC_ABUF;
                    #pragma unroll
                    for (int ks = 0; ks < 2; ks++) {
                        uint32_t ah[4], al[4];
                        ldsm4(ah, abase + a_offA + ks*32);
                        ldsm4(al, abase + 5120 + a_offA + ks*32);
                        uint32_t kb = (uint32_t)(c*32 + ks*16 + b_k8)*2;
                        #pragma unroll
                        for (int p = 0; p < 2; p++) {
                            uint32_t bh[4];
                            ldsm4(bh, smu + RC_WA + (uint32_t)(32*chA + 16*p + b_row)*BSTR*2 + kb);
                            mma16816(acc[2*p],   ah, bh[0], bh[1]);
                            mma16816(acc[2*p+1], ah, bh[2], bh[3]);
                            mma16816(acc[2*p],   al, bh[0], bh[1]);
                            mma16816(acc[2*p+1], al, bh[2], bh[3]);
                        }
                    }
                }
                int rowl = b0 + 16*mtA + (lane >> 2);
                #pragma unroll
                for (int nt = 0; nt < 4; nt++) {
                    int gc0 = 32*chA + 8*nt + 2*(lane & 3);
                    #pragma unroll
                    for (int rr = 0; rr < 2; rr++) {
                        int row = rowl + 8*rr;
                        const float* lx = Lxt + (size_t)row*NLX;
                        #pragma unroll
                        for (int jj = 0; jj < 2; jj++) {
                            int gc = gc0 + jj;
                            float a = acc[nt][2*rr + jj];
                            if (chA == 0) {
                                int j = j0 + gc;
                                g_zg[(size_t)row*KST + j] = fsigmoid(a + lx[j] + bg[j]);
                            } else {
                                int j = j0 + gc - 32;
                                size_t idx = (size_t)row*KST + j;
                                float r = fsigmoid(a + lx[KST + j] + bg[KST + j]);
                                split_store(g_us_hi, g_us_lo, idx, r * hin[idx]);
                            }
                        }
                    }
                }
            }
            grid_sync();

            // ================= phase B: lin GEMM + RK4 =================
            {
                float acc[2][4];
                acc[0][0]=0.f; acc[0][1]=0.f; acc[0][2]=0.f; acc[0][3]=0.f;
                acc[1][0]=0.f; acc[1][1]=0.f; acc[1][2]=0.f; acc[1][3]=0.f;
                const h16* shp = g_us_hi + arow_off;
                const h16* slp = g_us_lo + arow_off;
                #pragma unroll
                for (int c0 = 0; c0 < 2; c0++) {
                    uint32_t d = smu + RC_A + c0*RC_ABUF + sdst;
                    cp16(d,        shp + c0*32);
                    cp16(d + 5120, slp + c0*32);
                    CP_COMMIT();
                }
                #pragma unroll 1
                for (int c = 0; c < 16; c++) {
                    if (c < 15) { CP_WAIT(1); } else { CP_WAIT(0); }
                    __syncthreads();
                    if (c + 2 < 16) {
                        uint32_t d = smu + RC_A + ((c+2)%3)*RC_ABUF + sdst;
                        cp16(d,        shp + (c+2)*32);
                        cp16(d + 5120, slp + (c+2)*32);
                        CP_COMMIT();
                    }
                    uint32_t abase = smu + RC_A + (c%3)*RC_ABUF;
                    #pragma unroll
                    for (int ks = 0; ks < 2; ks++) {
                        uint32_t ah[4], al[4];
                        ldsm4(ah, abase + a_offA + ks*32);
                        ldsm4(al, abase + 5120 + a_offA + ks*32);
                        uint32_t kb = (uint32_t)(c*32 + ks*16 + b_k8)*2;
                        uint32_t bh[4];
                        ldsm4(bh, smu + RC_WB + (uint32_t)(coB + b_row)*BSTR*2 + kb);
                        mma16816(acc[0], ah, bh[0], bh[1]);
                        mma16816(acc[1], ah, bh[2], bh[3]);
                        mma16816(acc[0], al, bh[0], bh[1]);
                        mma16816(acc[1], al, bh[2], bh[3]);
                    }
                }
                int rowl = b0 + 16*mtA + (lane >> 2);
                #pragma unroll
                for (int rr = 0; rr < 2; rr++) {
                    int row = rowl + 8*rr;
                    float dt = (t > 0) ? seq[((size_t)(t-1)*B_SZ + row)*16 + 15] : 0.f;
                    const float* lx = Lxt + (size_t)row*NLX;
                    #pragma unroll
                    for (int nt = 0; nt < 2; nt++) {
                        int jl = coB + 8*nt + 2*(lane & 3);
                        #pragma unroll
                        for (int jj = 0; jj < 2; jj++) {
                            int j = j0 + jl + jj;
                            size_t idx = (size_t)row*KST + j;
                            float hv = hin[idx];
                            float kv = g_zg[idx] * (ftanh(acc[nt][2*rr + jj] + lx[2*KST + j] + blin[j]) - hv);
                            float ht;
                            if (s == 1)      { g_acc[idx]  = kv;      ht = g_h[idx] + dt*0.5f*kv; g_hA[idx] = ht; }
                            else if (s == 2) { g_acc[idx] += 2.f*kv;  ht = g_h[idx] + dt*0.5f*kv; g_hB[idx] = ht; }
                            else if (s == 3) { g_acc[idx] += 2.f*kv;  ht = g_h[idx] + dt*kv;      g_hA[idx] = ht; }
                            else {
                                ht = g_h[idx] + dt*(g_acc[idx] + kv)*(1.f/6.f);
                                g_h[idx] = ht;
                                split_store(g_st_hi, g_st_lo, (size_t)t*B_SZ*KST + idx, ht);
                            }
                            split_store(g_hs_hi, g_hs_lo, idx, ht);
                        }
                    }
                }
            }
            grid_sync();
        }
    }
}

// ---------------- out[1..255] = g_ty @ Ly2^T ----------------
__global__ void yout_kernel(const float* __restrict__ Ly2, float* __restrict__ out) {
    __shared__ float l2s[8*KST];
    int tid = threadIdx.x;
    for (int i = tid; i < 8*KST; i += 256) l2s[i] = Ly2[i];
    __syncthreads();
    int warp = tid >> 5, lane = tid & 31;
    int tok = blockIdx.x*8 + warp;
    const float* tr = g_ty + (size_t)tok*KST;
    float p[8] = {};
    for (int k = lane; k < KST; k += 32) {
        float tv = tr[k];
        #pragma unroll
        for (int o = 0; o < 8; o++) p[o] += tv*l2s[o*KST + k];
    }
    #pragma unroll
    for (int o = 0; o < 8; o++)
        #pragma unroll
        for (int off = 16; off; off >>= 1)
            p[o] += __shfl_xor_sync(0xffffffffu, p[o], off);
    if (lane == 0) {
        float* op = out + (size_t)(tok + B_SZ)*8;
        #pragma unroll
        for (int o = 0; o < 8; o++) op[o] = p[o];
    }
}

// ---------------- out[0] = Ly(h0) broadcast over batch ----------------
__global__ void y0_kernel(const float* __restrict__ state0,
                          const float* __restrict__ Ly1,
                          const float* __restrict__ Ly2,
                          float* __restrict__ out) {
    __shared__ float h0s[KST];
    __shared__ float tys[KST];
    __shared__ float y0s[8];
    int tid = threadIdx.x;
    for (int j = tid; j < KST; j += 256) h0s[j] = state0[j];
    __syncthreads();
    for (int j = tid; j < KST; j += 256) {
        float s = 0.f;
        const float* lr = Ly1 + (size_t)j*KST;
        for (int k = 0; k < KST; k++) s += h0s[k]*lr[k];
        tys[j] = tanhf(s);
    }
    __syncthreads();
    if (tid < 8) {
        float s = 0.f;
        const float* lr = Ly2 + (size_t)tid*KST;
        for (int k = 0; k < KST; k++) s += tys[k]*lr[k];
        y0s[tid] = s;
    }
    __syncthreads();
    for (int i = tid; i < B_SZ*8; i += 256) out[i] = y0s[i & 7];
}

// ---------------- launch ----------------
extern "C" void kernel_launch(void* const* d_in, const int* in_sizes, int n_in,
                              void* d_out, int out_size) {
    const float* seq    = (const float*)d_in[0];
    const float* state0 = (const float*)d_in[1];
    const float* Win    = (const float*)d_in[2];
    const float* bin    = (const float*)d_in[3];
    const float* Wx     = (const float*)d_in[4];
    const float* Wg     = (const float*)d_in[5];
    const float* bg     = (const float*)d_in[6];
    const float* Wlin   = (const float*)d_in[7];
    const float* blin   = (const float*)d_in[8];
    const float* Ly1    = (const float*)d_in[9];
    const float* Ly2    = (const float*)d_in[10];
    float* out = (float*)d_out;

    h16 *xeh, *xel, *sth, *stl;
    float *Lx, *ty;
    cudaGetSymbolAddress((void**)&xeh, g_xe_hi);
    cudaGetSymbolAddress((void**)&xel, g_xe_lo);
    cudaGetSymbolAddress((void**)&sth, g_st_hi);
    cudaGetSymbolAddress((void**)&stl, g_st_lo);
    cudaGetSymbolAddress((void**)&Lx,  g_Lx);
    cudaGetSymbolAddress((void**)&ty,  g_ty);

    cudaFuncSetAttribute(recur_mma, cudaFuncAttributeMaxDynamicSharedMemorySize, RC_SMEM);
    cudaFuncSetAttribute(gemm_split<0>, cudaFuncAttributeMaxDynamicSharedMemorySize, GS_SMEM);
    cudaFuncSetAttribute(gemm_split<1>, cudaFuncAttributeMaxDynamicSharedMemorySize, GS_SMEM);

    embed_kernel<<<NTOK, 128>>>(seq, Win, bin);
    gemm_split<0><<<dim3(NTOK/128, NLX/64), 256, GS_SMEM>>>(xeh, xel, Wx, Lx, NLX);

    recur_mma<<<NBR, 256, RC_SMEM>>>(seq, state0, Wg, bg, Wlin, blin);

    gemm_split<1><<<dim3((NTOK - B_SZ)/128, KST/64), 256, GS_SMEM>>>(sth, stl, Ly1, ty, KST);
    yout_kernel<<<(NTOK - B_SZ)/8, 256>>>(Ly2, out);
    y0_kernel<<<1, 256>>>(state0, Ly1, Ly2, out);
}

// round 17
// speedup vs baseline: 1.6645x; 1.0756x over previous
#include <cuda_runtime.h>
#include <cuda_bf16.h>
#include <cuda_fp16.h>
#include <math.h>
#include <stdint.h>

#define L_SEQ 256
#define B_SZ  512
#define KIN   15
#define KST   512
#define NLX   1536
#define NTOK  (L_SEQ*B_SZ)   // 131072
#define NBR   128            // persistent CTAs for recurrence
#define BSTR  520            // weight-slab row stride (fp16 elems), 1040B rows

typedef unsigned long long ull;
typedef __half h16;

// ---------------- scratch (device globals; no allocation) ----------------
__device__ __align__(16) h16 g_xe_hi[(size_t)NTOK*KST];
__device__ __align__(16) h16 g_xe_lo[(size_t)NTOK*KST];
__device__ float g_Lx[(size_t)NTOK*NLX];
__device__ __align__(16) h16 g_st_hi[(size_t)NTOK*KST];
__device__ __align__(16) h16 g_st_lo[(size_t)NTOK*KST];
__device__ float g_ty[(size_t)(NTOK-B_SZ)*KST];
__device__ float g_h  [B_SZ*KST];
__device__ float g_hA [B_SZ*KST];
__device__ float g_hB [B_SZ*KST];
__device__ float g_acc[B_SZ*KST];
__device__ float g_zg [B_SZ*KST];
__device__ __align__(16) h16 g_hs_hi[B_SZ*KST];
__device__ __align__(16) h16 g_hs_lo[B_SZ*KST];
__device__ __align__(16) h16 g_us_hi[B_SZ*KST];
__device__ __align__(16) h16 g_us_lo[B_SZ*KST];
__device__ unsigned g_bar_count = 0;
__device__ volatile unsigned g_bar_gen = 0;

// ---------------- MUFU-free activations (FMA pipe only) ----------------
__device__ __forceinline__ float fexp(float x) {
    float y = fminf(fmaxf(x*1.44269504f, -126.f), 126.f);
    float n = rintf(y);
    float t = (y - n)*0.69314718056f;
    float p = fmaf(t, 0.0013888889f, 0.0083333338f);
    p = fmaf(t, p, 0.041666668f);
    p = fmaf(t, p, 0.16666667f);
    p = fmaf(t, p, 0.5f);
    p = fmaf(t, p, 1.0f);
    p = fmaf(t, p, 1.0f);
    float sc = __int_as_float(((int)n + 127) << 23);
    return p*sc;
}
__device__ __forceinline__ float frecip(float d) {
    float r = __int_as_float(0x7EF311C3 - __float_as_int(d));
    r = r*fmaf(-d, r, 2.f);
    r = r*fmaf(-d, r, 2.f);
    r = r*fmaf(-d, r, 2.f);
    return r;
}
__device__ __forceinline__ float fsigmoid(float x) { return frecip(1.f + fexp(-x)); }
__device__ __forceinline__ float ftanh(float x) {
    return 1.f - 2.f*frecip(fexp(2.f*x) + 1.f);
}

// ---------------- warp-MMA + async-copy primitives (sm_80+ baseline PTX) ----------------
__device__ __forceinline__ uint32_t smem_u32(const void* p) {
    uint32_t a;
    asm("{ .reg .u64 t; cvta.to.shared.u64 t, %1; cvt.u32.u64 %0, t; }" : "=r"(a) : "l"(p));
    return a;
}
__device__ __forceinline__ void ldsm4(uint32_t* r, uint32_t addr) {
    asm volatile("ldmatrix.sync.aligned.m8n8.x4.shared.b16 {%0,%1,%2,%3}, [%4];"
        : "=r"(r[0]), "=r"(r[1]), "=r"(r[2]), "=r"(r[3]) : "r"(addr));
}
__device__ __forceinline__ void mma16816(float* d, const uint32_t* a, uint32_t b0, uint32_t b1) {
    asm volatile("mma.sync.aligned.m16n8k16.row.col.f32.f16.f16.f32 "
        "{%0,%1,%2,%3}, {%4,%5,%6,%7}, {%8,%9}, {%0,%1,%2,%3};"
        : "+f"(d[0]), "+f"(d[1]), "+f"(d[2]), "+f"(d[3])
        : "r"(a[0]), "r"(a[1]), "r"(a[2]), "r"(a[3]), "r"(b0), "r"(b1));
}
__device__ __forceinline__ void cp16(uint32_t dst, const void* src) {
    asm volatile("cp.async.cg.shared.global [%0], [%1], 16;" :: "r"(dst), "l"(src));
}
#define CP_COMMIT() asm volatile("cp.async.commit_group;" ::: "memory")
#define CP_WAIT(n)  asm volatile("cp.async.wait_group %0;" :: "n"(n) : "memory")

__device__ __forceinline__ void split_store(h16* hi, h16* lo, size_t idx, float v) {
    h16 h = __float2half_rn(v);
    hi[idx] = h;
    lo[idx] = __float2half_rn(v - __half2float(h));
}

// software grid barrier across NBR CTAs (tight spin; all CTAs resident 1/SM)
__device__ __forceinline__ void grid_sync() {
    __syncthreads();
    if (threadIdx.x == 0) {
        __threadfence();
        unsigned g = g_bar_gen;
        if (atomicAdd(&g_bar_count, 1u) == (unsigned)(NBR - 1)) {
            g_bar_count = 0;
            __threadfence();
            g_bar_gen = g + 1u;
        } else {
            while (g_bar_gen == g) { }
            __threadfence();
        }
    }
    __syncthreads();
}

// ---------------- xe = tanh(x @ Win^T + bin), split to fp16 hi/lo ----------------
__global__ void embed_kernel(const float* __restrict__ seq,
                             const float* __restrict__ Win,
                             const float* __restrict__ bin) {
    int tok = blockIdx.x;
    __shared__ float xs[KIN];
    if (threadIdx.x < KIN) xs[threadIdx.x] = seq[(size_t)tok*16 + threadIdx.x];
    __syncthreads();
    for (int j = threadIdx.x; j < KST; j += blockDim.x) {
        float s = bin[j];
        const float* wr = Win + j*KIN;
        #pragma unroll
        for (int i = 0; i < KIN; i++) s += xs[i]*wr[i];
        split_store(g_xe_hi, g_xe_lo, (size_t)tok*KST + j, ftanh(s));
    }
}

// ---------------- 2-pass split-fp16 GEMM: C = act(A @ B^T), tile 128x64, K=512 ----------------
// Chunk k=64, 3 bufs, depth-2 cp.async. 256 thr.
#define ASTR_G  72
#define GS_W    0               // 64 x 520 fp16 = 66560
#define GS_A    66560
#define GS_AHALF 18432          // 128 x 72 fp16
#define GS_ABUF 36864
#define GS_SMEM (GS_A + 3*GS_ABUF)   // 177152
template<int TANH>
__global__ void __launch_bounds__(256) gemm_split(
    const h16* __restrict__ Ahi, const h16* __restrict__ Alo,
    const float* __restrict__ B, float* __restrict__ C, int N)
{
    extern __shared__ char sm[];
    uint32_t smu = smem_u32(sm);
    int tid = threadIdx.x;
    int w = tid >> 5, lane = tid & 31;
    int bm = blockIdx.x*128, bn = blockIdx.y*64;

    for (int e = tid; e < 64*KST; e += 256) {
        int n = e >> 9, k = e & (KST-1);
        ((h16*)(sm + GS_W))[(size_t)n*BSTR + k] = __float2half_rn(B[(size_t)(bn + n)*KST + k]);
    }

    float acc[8][4];
    #pragma unroll
    for (int i = 0; i < 8; i++) { acc[i][0]=0.f; acc[i][1]=0.f; acc[i][2]=0.f; acc[i][3]=0.f; }

    uint32_t a_off = ((uint32_t)(16*w + (lane & 15))*ASTR_G + ((lane >> 4) << 3)) * 2;
    uint32_t b_row = (lane & 7) + ((lane & 16) >> 1);
    uint32_t b_k8  = (lane & 8);

    int srow = tid >> 1, skc = (tid & 1)*32;
    const h16* ahp = Ahi + (size_t)(bm + srow)*KST + skc;
    const h16* alp = Alo + (size_t)(bm + srow)*KST + skc;
    uint32_t sdst = (uint32_t)(srow*ASTR_G + skc)*2;

    #pragma unroll
    for (int c0 = 0; c0 < 2; c0++) {
        uint32_t d = smu + GS_A + c0*GS_ABUF + sdst;
        #pragma unroll
        for (int q = 0; q < 4; q++) {
            cp16(d + q*16,            ahp + c0*64 + q*8);
            cp16(d + GS_AHALF + q*16, alp + c0*64 + q*8);
        }
        CP_COMMIT();
    }
    __syncthreads();

    #pragma unroll 1
    for (int c = 0; c < 8; c++) {
        if (c < 7) { CP_WAIT(1); } else { CP_WAIT(0); }
        __syncthreads();
        if (c + 2 < 8) {
            uint32_t d = smu + GS_A + ((c+2)%3)*GS_ABUF + sdst;
            #pragma unroll
            for (int q = 0; q < 4; q++) {
                cp16(d + q*16,            ahp + (c+2)*64 + q*8);
                cp16(d + GS_AHALF + q*16, alp + (c+2)*64 + q*8);
            }
            CP_COMMIT();
        }
        uint32_t abase = smu + GS_A + (c%3)*GS_ABUF;
        #pragma unroll
        for (int ks = 0; ks < 4; ks++) {
            uint32_t ah[4], al[4];
            ldsm4(ah, abase + a_off + ks*32);
            ldsm4(al, abase + GS_AHALF + a_off + ks*32);
            uint32_t kb = (uint32_t)(c*64 + ks*16 + b_k8)*2;
            #pragma unroll
            for (int p = 0; p < 4; p++) {
                uint32_t bh[4];
                ldsm4(bh, smu + GS_W + (uint32_t)(16*p + b_row)*BSTR*2 + kb);
                mma16816(acc[2*p],   ah, bh[0], bh[1]);
                mma16816(acc[2*p+1], ah, bh[2], bh[3]);
                mma16816(acc[2*p],   al, bh[0], bh[1]);
                mma16816(acc[2*p+1], al, bh[2], bh[3]);
            }
        }
    }

    int rowl = bm + 16*w + (lane >> 2);
    #pragma unroll
    for (int nt = 0; nt < 8; nt++) {
        int col = bn + 8*nt + 2*(lane & 3);
        #pragma unroll
        for (int rr = 0; rr < 2; rr++) {
            size_t ro = (size_t)(rowl + 8*rr)*N + col;
            float v0 = acc[nt][2*rr], v1 = acc[nt][2*rr+1];
            if (TANH) { v0 = ftanh(v0); v1 = ftanh(v1); }
            C[ro] = v0; C[ro + 1] = v1;
        }
    }
}

// ---------------- persistent recurrence kernel (chunk=128, epilogue prefetch) ----------------
// 128 CTAs x 256 thr. CTA: b0 = (cta&7)*64 rows, j0 = (cta>>3)*32 state cols.
#define ASTR_R  136
#define RC_WA   0               // gates: 64 x 520 fp16 = 66560
#define RC_WB   66560           // lin:   32 x 520 fp16 = 33280
#define RC_A    99840
#define RC_AHALF 17408          // 64 x 136 fp16
#define RC_ABUF 34816
#define RC_SMEM (RC_A + 3*RC_ABUF)   // 204288
__global__ void __launch_bounds__(256, 1) recur_mma(
    const float* __restrict__ seq, const float* __restrict__ state0,
    const float* __restrict__ Wg, const float* __restrict__ bg,
    const float* __restrict__ Wlin, const float* __restrict__ blin)
{
    extern __shared__ char sm[];
    uint32_t smu = smem_u32(sm);
    int tid = threadIdx.x;
    int w = tid >> 5, lane = tid & 31;
    int cta = blockIdx.x;
    int b0 = (cta & 7)*64;
    int j0 = (cta >> 3)*32;

    for (int e = tid; e < 64*KST; e += 256) {
        int n = e >> 9, k = e & (KST-1);
        int grow = (n < 32) ? (j0 + n) : (KST + j0 + n - 32);
        ((h16*)(sm + RC_WA))[(size_t)n*BSTR + k] = __float2half_rn(Wg[(size_t)grow*KST + k]);
    }
    for (int e = tid; e < 32*KST; e += 256) {
        int n = e >> 9, k = e & (KST-1);
        ((h16*)(sm + RC_WB))[(size_t)n*BSTR + k] = __float2half_rn(Wlin[(size_t)(j0 + n)*KST + k]);
    }
    for (int idx = cta*256 + tid; idx < B_SZ*KST; idx += NBR*256) {
        float h0 = state0[idx & (KST-1)];
        g_h[idx] = h0;
        split_store(g_hs_hi, g_hs_lo, idx, h0);
    }
    grid_sync();

    int mtA = w & 3, chA = w >> 2;
    int coB = (w >> 2)*16;
    uint32_t a_offA = ((uint32_t)(16*mtA + (lane & 15))*ASTR_R + ((lane >> 4) << 3)) * 2;
    uint32_t b_row = (lane & 7) + ((lane & 16) >> 1);
    uint32_t b_k8  = (lane & 8);

    int srow = tid >> 2, skc = (tid & 3)*32;
    uint32_t sdst = (uint32_t)(srow*ASTR_R + skc)*2;
    const size_t arow_off = (size_t)(b0 + srow)*KST + skc;
    int rowl = b0 + 16*mtA + (lane >> 2);

    // hoisted biases (t-invariant)
    float bgp[8];
    #pragma unroll
    for (int nt = 0; nt < 4; nt++)
        #pragma unroll
        for (int jj = 0; jj < 2; jj++) {
            int gc = 32*chA + 8*nt + 2*(lane & 3) + jj;
            bgp[nt*2 + jj] = (chA == 0) ? bg[j0 + gc] : bg[KST + j0 + gc - 32];
        }
    float blp[4];
    #pragma unroll
    for (int nt = 0; nt < 2; nt++)
        #pragma unroll
        for (int jj = 0; jj < 2; jj++)
            blp[nt*2 + jj] = blin[j0 + coB + 8*nt + 2*(lane & 3) + jj];

    #pragma unroll 1
    for (int t = 0; t < L_SEQ; ++t) {
        const float* Lxt = g_Lx + (size_t)t*B_SZ*NLX;
        #pragma unroll 1
        for (int s = 1; s <= 4; ++s) {
            const float* hin = (s==1) ? g_h : (s==2 ? g_hA : (s==3 ? g_hB : g_hA));

            // ================= phase A: gate GEMM (z,r) =================
            {
                // epilogue operand prefetch (overlaps GEMM)
                float lxp[16], hinp[16];
                #pragma unroll
                for (int nt = 0; nt < 4; nt++) {
                    int gc0 = 32*chA + 8*nt + 2*(lane & 3);
                    #pragma unroll
                    for (int rr = 0; rr < 2; rr++) {
                        int row = rowl + 8*rr;
                        const float* lx = Lxt + (size_t)row*NLX;
                        #pragma unroll
                        for (int jj = 0; jj < 2; jj++) {
                            int e = nt*4 + rr*2 + jj;
                            if (chA == 0) {
                                lxp[e] = lx[j0 + gc0 + jj];
                            } else {
                                int j = j0 + gc0 + jj - 32;
                                lxp[e]  = lx[KST + j];
                                hinp[e] = hin[(size_t)row*KST + j];
                            }
                        }
                    }
                }

                float acc[4][4];
                #pragma unroll
                for (int i = 0; i < 4; i++) { acc[i][0]=0.f; acc[i][1]=0.f; acc[i][2]=0.f; acc[i][3]=0.f; }
                const h16* shp = g_hs_hi + arow_off;
                const h16* slp = g_hs_lo + arow_off;
                #pragma unroll
                for (int c0 = 0; c0 < 2; c0++) {
                    uint32_t d = smu + RC_A + c0*RC_ABUF + sdst;
                    #pragma unroll
                    for (int q = 0; q < 4; q++) {
                        cp16(d + q*16,            shp + c0*128 + q*8);
                        cp16(d + RC_AHALF + q*16, slp + c0*128 + q*8);
                    }
                    CP_COMMIT();
                }
                #pragma unroll 1
                for (int c = 0; c < 4; c++) {
                    if (c < 3) { CP_WAIT(1); } else { CP_WAIT(0); }
                    __syncthreads();
                    if (c + 2 < 4) {
                        uint32_t d = smu + RC_A + ((c+2)%3)*RC_ABUF + sdst;
                        #pragma unroll
                        for (int q = 0; q < 4; q++) {
                            cp16(d + q*16,            shp + (c+2)*128 + q*8);
                            cp16(d + RC_AHALF + q*16, slp + (c+2)*128 + q*8);
                        }
                        CP_COMMIT();
                    }
                    uint32_t abase = smu + RC_A + (c%3)*RC_ABUF;
                    #pragma unroll
                    for (int ks = 0; ks < 8; ks++) {
                        uint32_t ah[4], al[4];
                        ldsm4(ah, abase + a_offA + ks*32);
                        ldsm4(al, abase + RC_AHALF + a_offA + ks*32);
                        uint32_t kb = (uint32_t)(c*128 + ks*16 + b_k8)*2;
                        #pragma unroll
                        for (int p = 0; p < 2; p++) {
                            uint32_t bh[4];
                            ldsm4(bh, smu + RC_WA + (uint32_t)(32*chA + 16*p + b_row)*BSTR*2 + kb);
                            mma16816(acc[2*p],   ah, bh[0], bh[1]);
                            mma16816(acc[2*p+1], ah, bh[2], bh[3]);
                            mma16816(acc[2*p],   al, bh[0], bh[1]);
                            mma16816(acc[2*p+1], al, bh[2], bh[3]);
                        }
                    }
                }
                // gate epilogue (prefetched operands)
                #pragma unroll
                for (int nt = 0; nt < 4; nt++) {
                    int gc0 = 32*chA + 8*nt + 2*(lane & 3);
                    #pragma unroll
                    for (int rr = 0; rr < 2; rr++) {
                        int row = rowl + 8*rr;
                        #pragma unroll
                        for (int jj = 0; jj < 2; jj++) {
                            int e = nt*4 + rr*2 + jj;
                            float a = acc[nt][2*rr + jj];
                            if (chA == 0) {
                                int j = j0 + gc0 + jj;
                                g_zg[(size_t)row*KST + j] = fsigmoid(a + lxp[e] + bgp[nt*2 + jj]);
                            } else {
                                int j = j0 + gc0 + jj - 32;
                                size_t idx = (size_t)row*KST + j;
                                float r = fsigmoid(a + lxp[e] + bgp[nt*2 + jj]);
                                split_store(g_us_hi, g_us_lo, idx, r * hinp[e]);
                            }
                        }
                    }
                }
            }
            grid_sync();

            // ================= phase B: lin GEMM + RK4 =================
            {
                // epilogue operand prefetch
                float lx2[8], zgp[8], hvp[8], dtp[2];
                #pragma unroll
                for (int rr = 0; rr < 2; rr++) {
                    int row = rowl + 8*rr;
                    dtp[rr] = (t > 0) ? seq[((size_t)(t-1)*B_SZ + row)*16 + 15] : 0.f;
                    const float* lx = Lxt + (size_t)row*NLX;
                    #pragma unroll
                    for (int nt = 0; nt < 2; nt++) {
                        #pragma unroll
                        for (int jj = 0; jj < 2; jj++) {
                            int j = j0 + coB + 8*nt + 2*(lane & 3) + jj;
                            int e = nt*4 + rr*2 + jj;
                            size_t idx = (size_t)row*KST + j;
                            lx2[e] = lx[2*KST + j];
                            zgp[e] = g_zg[idx];
                            hvp[e] = hin[idx];
                        }
                    }
                }

                float acc[2][4];
                acc[0][0]=0.f; acc[0][1]=0.f; acc[0][2]=0.f; acc[0][3]=0.f;
                acc[1][0]=0.f; acc[1][1]=0.f; acc[1][2]=0.f; acc[1][3]=0.f;
                const h16* shp = g_us_hi + arow_off;
                const h16* slp = g_us_lo + arow_off;
                #pragma unroll
                for (int c0 = 0; c0 < 2; c0++) {
                    uint32_t d = smu + RC_A + c0*RC_ABUF + sdst;
                    #pragma unroll
                    for (int q = 0; q < 4; q++) {
                        cp16(d + q*16,            shp + c0*128 + q*8);
                        cp16(d + RC_AHALF + q*16, slp + c0*128 + q*8);
                    }
                    CP_COMMIT();
                }
                #pragma unroll 1
                for (int c = 0; c < 4; c++) {
                    if (c < 3) { CP_WAIT(1); } else { CP_WAIT(0); }
                    __syncthreads();
                    if (c + 2 < 4) {
                        uint32_t d = smu + RC_A + ((c+2)%3)*RC_ABUF + sdst;
                        #pragma unroll
                        for (int q = 0; q < 4; q++) {
                            cp16(d + q*16,            shp + (c+2)*128 + q*8);
                            cp16(d + RC_AHALF + q*16, slp + (c+2)*128 + q*8);
                        }
                        CP_COMMIT();
                    }
                    uint32_t abase = smu + RC_A + (c%3)*RC_ABUF;
                    #pragma unroll
                    for (int ks = 0; ks < 8; ks++) {
                        uint32_t ah[4], al[4];
                        ldsm4(ah, abase + a_offA + ks*32);
                        ldsm4(al, abase + RC_AHALF + a_offA + ks*32);
                        uint32_t kb = (uint32_t)(c*128 + ks*16 + b_k8)*2;
                        uint32_t bh[4];
                        ldsm4(bh, smu + RC_WB + (uint32_t)(coB + b_row)*BSTR*2 + kb);
                        mma16816(acc[0], ah, bh[0], bh[1]);
                        mma16816(acc[1], ah, bh[2], bh[3]);
                        mma16816(acc[0], al, bh[0], bh[1]);
                        mma16816(acc[1], al, bh[2], bh[3]);
                    }
                }
                // RK4 epilogue (prefetched operands)
                #pragma unroll
                for (int rr = 0; rr < 2; rr++) {
                    int row = rowl + 8*rr;
                    float dt = dtp[rr];
                    #pragma unroll
                    for (int nt = 0; nt < 2; nt++) {
                        #pragma unroll
                        for (int jj = 0; jj < 2; jj++) {
                            int j = j0 + coB + 8*nt + 2*(lane & 3) + jj;
                            int e = nt*4 + rr*2 + jj;
                            size_t idx = (size_t)row*KST + j;
                            float hv = hvp[e];
                            float kv = zgp[e] * (ftanh(acc[nt][2*rr + jj] + lx2[e] + blp[nt*2 + jj]) - hv);
                            float ht;
                            if (s == 1)      { g_acc[idx]  = kv;      ht = g_h[idx] + dt*0.5f*kv; g_hA[idx] = ht; }
                            else if (s == 2) { g_acc[idx] += 2.f*kv;  ht = g_h[idx] + dt*0.5f*kv; g_hB[idx] = ht; }
                            else if (s == 3) { g_acc[idx] += 2.f*kv;  ht = g_h[idx] + dt*kv;      g_hA[idx] = ht; }
                            else {
                                ht = g_h[idx] + dt*(g_acc[idx] + kv)*(1.f/6.f);
                                g_h[idx] = ht;
                                split_store(g_st_hi, g_st_lo, (size_t)t*B_SZ*KST + idx, ht);
                            }
                            split_store(g_hs_hi, g_hs_lo, idx, ht);
                        }
                    }
                }
            }
            grid_sync();
        }
    }
}

// ---------------- out[1..255] = g_ty @ Ly2^T ----------------
__global__ void yout_kernel(const float* __restrict__ Ly2, float* __restrict__ out) {
    __shared__ float l2s[8*KST];
    int tid = threadIdx.x;
    for (int i = tid; i < 8*KST; i += 256) l2s[i] = Ly2[i];
    __syncthreads();
    int warp = tid >> 5, lane = tid & 31;
    int tok = blockIdx.x*8 + warp;
    const float* tr = g_ty + (size_t)tok*KST;
    float p[8] = {};
    for (int k = lane; k < KST; k += 32) {
        float tv = tr[k];
        #pragma unroll
        for (int o = 0; o < 8; o++) p[o] += tv*l2s[o*KST + k];
    }
    #pragma unroll
    for (int o = 0; o < 8; o++)
        #pragma unroll
        for (int off = 16; off; off >>= 1)
            p[o] += __shfl_xor_sync(0xffffffffu, p[o], off);
    if (lane == 0) {
        float* op = out + (size_t)(tok + B_SZ)*8;
        #pragma unroll
        for (int o = 0; o < 8; o++) op[o] = p[o];
    }
}

// ---------------- out[0] = Ly(h0) broadcast over batch ----------------
__global__ void y0_kernel(const float* __restrict__ state0,
                          const float* __restrict__ Ly1,
                          const float* __restrict__ Ly2,
                          float* __restrict__ out) {
    __shared__ float h0s[KST];
    __shared__ float tys[KST];
    __shared__ float y0s[8];
    int tid = threadIdx.x;
    for (int j = tid; j < KST; j += 256) h0s[j] = state0[j];
    __syncthreads();
    for (int j = tid; j < KST; j += 256) {
        float s = 0.f;
        const float* lr = Ly1 + (size_t)j*KST;
        for (int k = 0; k < KST; k++) s += h0s[k]*lr[k];
        tys[j] = tanhf(s);
    }
    __syncthreads();
    if (tid < 8) {
        float s = 0.f;
        const float* lr = Ly2 + (size_t)tid*KST;
        for (int k = 0; k < KST; k++) s += tys[k]*lr[k];
        y0s[tid] = s;
    }
    __syncthreads();
    for (int i = tid; i < B_SZ*8; i += 256) out[i] = y0s[i & 7];
}

// ---------------- launch ----------------
extern "C" void kernel_launch(void* const* d_in, const int* in_sizes, int n_in,
                              void* d_out, int out_size) {
    const float* seq    = (const float*)d_in[0];
    const float* state0 = (const float*)d_in[1];
    const float* Win    = (const float*)d_in[2];
    const float* bin    = (const float*)d_in[3];
    const float* Wx     = (const float*)d_in[4];
    const float* Wg     = (const float*)d_in[5];
    const float* bg     = (const float*)d_in[6];
    const float* Wlin   = (const float*)d_in[7];
    const float* blin   = (const float*)d_in[8];
    const float* Ly1    = (const float*)d_in[9];
    const float* Ly2    = (const float*)d_in[10];
    float* out = (float*)d_out;

    h16 *xeh, *xel, *sth, *stl;
    float *Lx, *ty;
    cudaGetSymbolAddress((void**)&xeh, g_xe_hi);
    cudaGetSymbolAddress((void**)&xel, g_xe_lo);
    cudaGetSymbolAddress((void**)&sth, g_st_hi);
    cudaGetSymbolAddress((void**)&stl, g_st_lo);
    cudaGetSymbolAddress((void**)&Lx,  g_Lx);
    cudaGetSymbolAddress((void**)&ty,  g_ty);

    cudaFuncSetAttribute(recur_mma, cudaFuncAttributeMaxDynamicSharedMemorySize, RC_SMEM);
    cudaFuncSetAttribute(gemm_split<0>, cudaFuncAttributeMaxDynamicSharedMemorySize, GS_SMEM);
    cudaFuncSetAttribute(gemm_split<1>, cudaFuncAttributeMaxDynamicSharedMemorySize, GS_SMEM);

    embed_kernel<<<NTOK, 128>>>(seq, Win, bin);
    gemm_split<0><<<dim3(NTOK/128, NLX/64), 256, GS_SMEM>>>(xeh, xel, Wx, Lx, NLX);

    recur_mma<<<NBR, 256, RC_SMEM>>>(seq, state0, Wg, bg, Wlin, blin);

    gemm_split<1><<<dim3((NTOK - B_SZ)/128, KST/64), 256, GS_SMEM>>>(sth, stl, Ly1, ty, KST);
    yout_kernel<<<(NTOK - B_SZ)/8, 256>>>(Ly2, out);
    y0_kernel<<<1, 256>>>(state0, Ly1, Ly2, out);
}